// round 1
// baseline (speedup 1.0000x reference)
#include <cuda_runtime.h>
#include <math.h>

// ---------------------------------------------------------------------------
// Problem constants (fixed by the reference)
// ---------------------------------------------------------------------------
namespace {
constexpr int BATCH = 8;
constexpr int HWD   = 128;                 // H == W == 128
constexpr int DIM   = 256;
constexpr int CA    = 128;                 // attention channels (DIM/2)
constexpr int NWIN  = 256;                 // (128/8)^2 windows
constexpr int NTOK  = 64;                  // 8*8 tokens per window
constexpr int LTOT  = BATCH * HWD * HWD;   // 131072 tokens
constexpr int QKV_ROWS = 2 * BATCH * NWIN * NTOK; // 262144 (both branches)
constexpr int HID   = 512;                 // mlp hidden
}
#define QSCALE 0.17677669529663687f        /* 32^-0.5 */

// ---------------------------------------------------------------------------
// Scratch (device globals; no allocation allowed)
// ---------------------------------------------------------------------------
__device__ float g_xn [(size_t)LTOT * DIM];          // LN1 output
__device__ float g_qkv[(size_t)QKV_ROWS * 384];      // qkv per window token
__device__ float g_qg [(size_t)2*8*128*256];         // grad score q (p,b,c,win)
__device__ float g_kg [(size_t)2*8*128*256];         // grad score k
__device__ float g_vt [(size_t)2*8*128*256*64];      // v transposed (p,b,c,win,tok)
__device__ float g_ao [(size_t)QKV_ROWS * 128];      // attention out (p,b,win,tok,c)
__device__ float g_y  [(size_t)LTOT * DIM];          // shortcut + attn
__device__ float g_z  [(size_t)LTOT * DIM];          // LN2 output
__device__ float g_t  [(size_t)LTOT * HID];          // fc1 output
__device__ float g_g  [(size_t)LTOT * DIM];          // gate output

// ---------------------------------------------------------------------------
// Row <-> spatial mapping.  Window row r = ((p*8+b)*256 + win)*64 + tok.
// Branch p==1 rolls by (-4,-4) on gather; the inverse roll on scatter is the
// SAME (+4,+4) index map, so one function serves both QKV-gather and
// PROJ-scatter.
// ---------------------------------------------------------------------------
__device__ __forceinline__ size_t spatial_idx(int r) {
    int p   = r >> 17;
    int rem = r & 131071;
    int b   = rem >> 14;
    int win = (rem >> 6) & 255;
    int t   = rem & 63;
    int hh  = ((win >> 4) << 3) + (t >> 3);
    int ww  = ((win & 15) << 3) + (t & 7);
    if (p) { hh = (hh + 4) & 127; ww = (ww + 4) & 127; }
    return ((size_t)(b * 16384 + hh * 128 + ww)) * 256 + p * 128;
}

// ---------------------------------------------------------------------------
// LayerNorm (one block per token row, 256 threads)
// MODE 0: in = param (x)  -> g_xn ; MODE 1: in = g_y -> g_z
// ---------------------------------------------------------------------------
template <int MODE>
__global__ __launch_bounds__(256) void ln_kernel(
    const float* __restrict__ in_ext,
    const float* __restrict__ gamma, const float* __restrict__ beta)
{
    __shared__ float s1[8], s2[8];
    const float* in = (MODE == 0) ? in_ext : g_y;
    float* out      = (MODE == 0) ? g_xn  : g_z;
    size_t base = (size_t)blockIdx.x * 256;
    int tid = threadIdx.x;
    float v = in[base + tid];
    float a = v, q = v * v;
    #pragma unroll
    for (int o = 16; o > 0; o >>= 1) {
        a += __shfl_xor_sync(0xffffffffu, a, o);
        q += __shfl_xor_sync(0xffffffffu, q, o);
    }
    if ((tid & 31) == 0) { s1[tid >> 5] = a; s2[tid >> 5] = q; }
    __syncthreads();
    float suma = 0.f, sumq = 0.f;
    #pragma unroll
    for (int w = 0; w < 8; w++) { suma += s1[w]; sumq += s2[w]; }
    float mean = suma * (1.f / 256.f);
    float var  = sumq * (1.f / 256.f) - mean * mean;
    float inv  = rsqrtf(var + 1e-5f);
    out[base + tid] = (v - mean) * inv * gamma[tid] + beta[tid];
}

// ---------------------------------------------------------------------------
// Shared fp32 GEMM: C = A @ W^T (+bias, +mode-specific epilogue)
// 128x128 block tile, BK=16, 256 threads, 8x8 micro-tile, float4 smem reads.
// MODE binds A / C / epilogue to the right scratch globals (no symbol-address
// lookups on the host side).
// ---------------------------------------------------------------------------
enum { M_QKV = 0, M_PROJ = 1, M_FC1 = 2, M_FC2 = 3 };

template <int MODE, int K>
__global__ __launch_bounds__(256) void gemm_kernel(
    const float* __restrict__ Wt,   // (Nout, K) row-major
    const float* __restrict__ bias,
    const float* __restrict__ ext_in,   // PROJ: shortcut x
    float* __restrict__ ext_out)        // FC2: d_out
{
    __shared__ __align__(16) float As[16][132];
    __shared__ __align__(16) float Bs[16][132];
    const int m0 = blockIdx.x * 128;
    const int n0 = blockIdx.y * 128;
    const int tid = threadIdx.x;
    const int tx = tid & 15, ty = tid >> 4;

    const float* Abase =
        (MODE == M_PROJ) ? g_ao :
        (MODE == M_FC1)  ? g_z  :
        (MODE == M_FC2)  ? g_g  : (const float*)0;

    float acc[8][8];
    #pragma unroll
    for (int i = 0; i < 8; i++)
        #pragma unroll
        for (int j = 0; j < 8; j++) acc[i][j] = 0.f;

    for (int k0 = 0; k0 < K; k0 += 16) {
        #pragma unroll
        for (int it = 0; it < 2; it++) {
            int idx = tid + it * 256;
            int m = idx >> 2, kq = idx & 3;
            const float* rp;
            if (MODE == M_QKV) rp = g_xn + spatial_idx(m0 + m);
            else               rp = Abase + (size_t)(m0 + m) * K;
            float4 va = *(const float4*)(rp + k0 + kq * 4);
            As[kq*4+0][m] = va.x; As[kq*4+1][m] = va.y;
            As[kq*4+2][m] = va.z; As[kq*4+3][m] = va.w;
            float4 vb = *(const float4*)(Wt + (size_t)(n0 + m) * K + k0 + kq * 4);
            Bs[kq*4+0][m] = vb.x; Bs[kq*4+1][m] = vb.y;
            Bs[kq*4+2][m] = vb.z; Bs[kq*4+3][m] = vb.w;
        }
        __syncthreads();
        #pragma unroll
        for (int k = 0; k < 16; k++) {
            float4 a0 = *(const float4*)&As[k][ty*8];
            float4 a1 = *(const float4*)&As[k][ty*8+4];
            float4 b0 = *(const float4*)&Bs[k][tx*8];
            float4 b1 = *(const float4*)&Bs[k][tx*8+4];
            float av[8] = {a0.x,a0.y,a0.z,a0.w,a1.x,a1.y,a1.z,a1.w};
            float bv[8] = {b0.x,b0.y,b0.z,b0.w,b1.x,b1.y,b1.z,b1.w};
            #pragma unroll
            for (int i = 0; i < 8; i++)
                #pragma unroll
                for (int j = 0; j < 8; j++)
                    acc[i][j] = fmaf(av[i], bv[j], acc[i][j]);
        }
        __syncthreads();
    }

    #pragma unroll
    for (int i = 0; i < 8; i++) {
        int row = m0 + ty*8 + i;
        #pragma unroll
        for (int j = 0; j < 8; j++) {
            int col = n0 + tx*8 + j;
            float val = acc[i][j] + bias[col];
            if (MODE == M_QKV) {
                g_qkv[(size_t)row * 384 + col] = val;
            } else if (MODE == M_PROJ) {
                size_t idx = spatial_idx(row) + col;   // scatter + un-roll
                g_y[idx] = ext_in[idx] + val;          // shortcut residual
            } else if (MODE == M_FC1) {
                g_t[(size_t)row * 512 + col] = val;
            } else { // M_FC2
                size_t idx = (size_t)row * 256 + col;
                ext_out[idx] = g_y[idx] + val;         // final residual
            }
        }
    }
}

// ---------------------------------------------------------------------------
// Grad scores + V transpose. One block per (p,b,win) = 4096 blocks.
// Score(t) = sum_{8x8} |gx|+|gy| with zero-prepend finite differences.
// ---------------------------------------------------------------------------
__global__ __launch_bounds__(256) void gradv_kernel() {
    __shared__ float buf[64][130];
    int blk = blockIdx.x;          // pb*256 + win
    int win = blk & 255;
    int pb  = blk >> 8;
    const float* qkv = g_qkv + (size_t)blk * 64 * 384;
    int tid = threadIdx.x;

    #pragma unroll
    for (int phase = 0; phase < 2; phase++) {      // 0 = Q, 1 = K
        for (int idx = tid; idx < 64*128; idx += 256)
            buf[idx >> 7][idx & 127] = qkv[(size_t)(idx >> 7) * 384 + phase*128 + (idx & 127)];
        __syncthreads();
        if (tid < 128) {
            float s = 0.f;
            #pragma unroll
            for (int tr = 0; tr < 8; tr++)
                #pragma unroll
                for (int tc = 0; tc < 8; tc++) {
                    float v = buf[tr*8+tc][tid];
                    float l = tc ? buf[tr*8+tc-1][tid] : 0.f;
                    float u = tr ? buf[(tr-1)*8+tc][tid] : 0.f;
                    s += fabsf(v - l) + fabsf(v - u);
                }
            size_t o = ((size_t)pb * 128 + tid) * 256 + win;
            if (phase == 0) g_qg[o] = s * QSCALE;  // q was scaled pre-grad; linear+abs
            else            g_kg[o] = s;
        }
        __syncthreads();
    }
    // V: load tile, write channel-contiguous transpose (p,b,c,win,tok)
    for (int idx = tid; idx < 64*128; idx += 256)
        buf[idx >> 7][idx & 127] = qkv[(size_t)(idx >> 7) * 384 + 256 + (idx & 127)];
    __syncthreads();
    for (int idx = tid; idx < 64*128; idx += 256) {
        int c = idx >> 6, t = idx & 63;
        g_vt[(((size_t)pb * 128 + c) * 256 + win) * 64 + t] = buf[t][c];
    }
}

// ---------------------------------------------------------------------------
// Rank-1-score softmax attention over windows. One block per (p,b,c) = 2048.
// Row max is max(qg_i*kmax, qg_i*kmin) -- no n^2 max pass needed.
// t split into two 32-wide halves to stay under 48KB static smem; Z reused.
// ---------------------------------------------------------------------------
__global__ __launch_bounds__(256) void attn_kernel() {
    __shared__ float kg_s[256];
    __shared__ __align__(16) float v_s[256*32];
    int blk = blockIdx.x;          // pb*128 + c
    int c  = blk & 127;
    int pb = blk >> 7;
    int tid = threadIdx.x;         // == output window index i
    const float* kg = g_kg + (size_t)blk * 256;
    const float* qg = g_qg + (size_t)blk * 256;
    const float* v  = g_vt + (size_t)blk * (256*64);

    kg_s[tid] = kg[tid];
    __syncthreads();
    float kmax = -1e30f, kmin = 1e30f;
    for (int j = 0; j < 256; j++) {
        float kv = kg_s[j];
        kmax = fmaxf(kmax, kv); kmin = fminf(kmin, kv);
    }
    float qgi = qg[tid];
    float m = fmaxf(qgi * kmax, qgi * kmin);
    float Z = 0.f, invZ = 0.f;

    for (int half = 0; half < 2; half++) {
        __syncthreads();
        for (int idx = tid; idx < 256*32; idx += 256) {
            int j = idx >> 5, tt = idx & 31;
            v_s[j*32 + tt] = v[(size_t)j*64 + half*32 + tt];
        }
        __syncthreads();
        float acc[32];
        #pragma unroll
        for (int t = 0; t < 32; t++) acc[t] = 0.f;
        for (int j = 0; j < 256; j++) {
            float w = __expf(fmaf(qgi, kg_s[j], -m));
            if (half == 0) Z += w;
            const float4* vp = (const float4*)(v_s + j*32);
            #pragma unroll
            for (int q4 = 0; q4 < 8; q4++) {
                float4 vv = vp[q4];
                acc[q4*4+0] = fmaf(w, vv.x, acc[q4*4+0]);
                acc[q4*4+1] = fmaf(w, vv.y, acc[q4*4+1]);
                acc[q4*4+2] = fmaf(w, vv.z, acc[q4*4+2]);
                acc[q4*4+3] = fmaf(w, vv.w, acc[q4*4+3]);
            }
        }
        if (half == 0) invZ = 1.f / Z;
        size_t ob = (((size_t)pb*256 + tid) * 64 + half*32) * 128 + c;
        #pragma unroll
        for (int t = 0; t < 32; t++) g_ao[ob + (size_t)t*128] = acc[t] * invZ;
    }
}

// ---------------------------------------------------------------------------
// Depthwise 3x3 conv (NCHW logical, channel-last storage) + gate x1*x2.
// One block per (b, hh) row, thread = channel c (computes c and c+256 convs).
// ---------------------------------------------------------------------------
__global__ __launch_bounds__(256) void gate_kernel(
    const float* __restrict__ dww, const float* __restrict__ dwb)
{
    int bh = blockIdx.x;
    int b  = bh >> 7;
    int hh = bh & 127;
    int c  = threadIdx.x;
    float w1[9], w2[9];
    #pragma unroll
    for (int k = 0; k < 9; k++) {
        w1[k] = dww[c*9 + k];
        w2[k] = dww[(c+256)*9 + k];
    }
    float b1 = dwb[c], b2 = dwb[c+256];
    const float* tb = g_t + (size_t)b * 16384 * 512;
    for (int ww = 0; ww < 128; ww++) {
        float s1 = b1, s2 = b2;
        #pragma unroll
        for (int dy = -1; dy <= 1; dy++) {
            int hy = hh + dy;
            if ((unsigned)hy < 128u) {
                #pragma unroll
                for (int dx = -1; dx <= 1; dx++) {
                    int wx = ww + dx;
                    if ((unsigned)wx < 128u) {
                        size_t off = ((size_t)hy * 128 + wx) * 512;
                        int kk = (dy+1)*3 + (dx+1);
                        s1 = fmaf(w1[kk], tb[off + c],       s1);
                        s2 = fmaf(w2[kk], tb[off + 256 + c], s2);
                    }
                }
            }
        }
        g_g[((size_t)b * 16384 + hh * 128 + ww) * 256 + c] = s1 * s2;
    }
}

// ---------------------------------------------------------------------------
// Launch: 9 kernels on the default stream (graph-capturable, allocation-free)
// ---------------------------------------------------------------------------
extern "C" void kernel_launch(void* const* d_in, const int* in_sizes, int n_in,
                              void* d_out, int out_size) {
    (void)in_sizes; (void)n_in; (void)out_size;
    const float* x     = (const float*)d_in[0];
    const float* n1g   = (const float*)d_in[1];
    const float* n1b   = (const float*)d_in[2];
    const float* qkvw  = (const float*)d_in[3];
    const float* qkvb  = (const float*)d_in[4];
    const float* projw = (const float*)d_in[5];
    const float* projb = (const float*)d_in[6];
    const float* n2g   = (const float*)d_in[7];
    const float* n2b   = (const float*)d_in[8];
    const float* fc1w  = (const float*)d_in[9];
    const float* fc1b  = (const float*)d_in[10];
    const float* dww   = (const float*)d_in[11];
    const float* dwb   = (const float*)d_in[12];
    const float* fc2w  = (const float*)d_in[13];
    const float* fc2b  = (const float*)d_in[14];
    float* out = (float*)d_out;

    ln_kernel<0><<<LTOT, 256>>>(x, n1g, n1b);
    gemm_kernel<M_QKV, 128><<<dim3(QKV_ROWS/128, 3), 256>>>(qkvw, qkvb, (const float*)0, (float*)0);
    gradv_kernel<<<2*BATCH*NWIN, 256>>>();
    attn_kernel<<<2*BATCH*128, 256>>>();
    gemm_kernel<M_PROJ, 128><<<dim3(QKV_ROWS/128, 1), 256>>>(projw, projb, x, (float*)0);
    ln_kernel<1><<<LTOT, 256>>>((const float*)0, n2g, n2b);
    gemm_kernel<M_FC1, 256><<<dim3(LTOT/128, 4), 256>>>(fc1w, fc1b, (const float*)0, (float*)0);
    gate_kernel<<<BATCH*HWD, 256>>>(dww, dwb);
    gemm_kernel<M_FC2, 256><<<dim3(LTOT/128, 2), 256>>>(fc2w, fc2b, (const float*)0, out);
}

// round 4
// speedup vs baseline: 1.9662x; 1.9662x over previous
#include <cuda_runtime.h>
#include <math.h>
#include <stdint.h>

// ---------------------------------------------------------------------------
// Problem constants
// ---------------------------------------------------------------------------
namespace {
constexpr int BATCH = 8;
constexpr int HWD   = 128;
constexpr int DIM   = 256;
constexpr int NWIN  = 256;
constexpr int NTOK  = 64;
constexpr int LTOT  = BATCH * HWD * HWD;            // 131072
constexpr int QKV_ROWS = 2 * BATCH * NWIN * NTOK;   // 262144
constexpr int HID   = 512;
}
#define QSCALE 0.17677669529663687f  /* 32^-0.5 */

// ---------------------------------------------------------------------------
// Scratch (device globals)
// ---------------------------------------------------------------------------
__device__ float g_xn [(size_t)LTOT * DIM];
__device__ float g_qkv[(size_t)QKV_ROWS * 384];
__device__ float g_qg [(size_t)2*8*128*256];
__device__ float g_kg [(size_t)2*8*128*256];
__device__ float g_vt [(size_t)2*8*128*256*64];
__device__ float g_ao [(size_t)QKV_ROWS * 128];
__device__ float g_y  [(size_t)LTOT * DIM];
__device__ float g_z  [(size_t)LTOT * DIM];
__device__ float g_t  [(size_t)LTOT * HID];
__device__ float g_g  [(size_t)LTOT * DIM];

// ---------------------------------------------------------------------------
// Window row -> spatial index (handles roll for branch p=1; self-inverse map
// serves both QKV gather and PROJ scatter).
// ---------------------------------------------------------------------------
__device__ __forceinline__ size_t spatial_idx(int r) {
    int p   = r >> 17;
    int rem = r & 131071;
    int b   = rem >> 14;
    int win = (rem >> 6) & 255;
    int t   = rem & 63;
    int hh  = ((win >> 4) << 3) + (t >> 3);
    int ww  = ((win & 15) << 3) + (t & 7);
    if (p) { hh = (hh + 4) & 127; ww = (ww + 4) & 127; }
    return ((size_t)(b * 16384 + hh * 128 + ww)) * 256 + p * 128;
}

// ---------------------------------------------------------------------------
// tf32 helpers.  cvt.rna.tf32.f32 requires a .b32 destination register.
// The result is a valid fp32 bit pattern, so we can keep smem as float.
// ---------------------------------------------------------------------------
__device__ __forceinline__ float to_tf32(float x) {
    uint32_t y;
    asm("cvt.rna.tf32.f32 %0, %1;" : "=r"(y) : "f"(x));
    return __uint_as_float(y);
}
__device__ __forceinline__ void mma8(float* c, const uint32_t* a,
                                     uint32_t b0, uint32_t b1) {
    asm volatile(
        "mma.sync.aligned.m16n8k8.row.col.f32.tf32.tf32.f32 "
        "{%0,%1,%2,%3},{%4,%5,%6,%7},{%8,%9},{%0,%1,%2,%3};"
        : "+f"(c[0]), "+f"(c[1]), "+f"(c[2]), "+f"(c[3])
        : "r"(a[0]), "r"(a[1]), "r"(a[2]), "r"(a[3]), "r"(b0), "r"(b1));
}

// ---------------------------------------------------------------------------
// LayerNorm (one block per token row, 256 threads)
// ---------------------------------------------------------------------------
template <int MODE>
__global__ __launch_bounds__(256) void ln_kernel(
    const float* __restrict__ in_ext,
    const float* __restrict__ gamma, const float* __restrict__ beta)
{
    __shared__ float s1[8], s2[8];
    const float* in = (MODE == 0) ? in_ext : g_y;
    float* out      = (MODE == 0) ? g_xn  : g_z;
    size_t base = (size_t)blockIdx.x * 256;
    int tid = threadIdx.x;
    float v = in[base + tid];
    float a = v, q = v * v;
    #pragma unroll
    for (int o = 16; o > 0; o >>= 1) {
        a += __shfl_xor_sync(0xffffffffu, a, o);
        q += __shfl_xor_sync(0xffffffffu, q, o);
    }
    if ((tid & 31) == 0) { s1[tid >> 5] = a; s2[tid >> 5] = q; }
    __syncthreads();
    float suma = 0.f, sumq = 0.f;
    #pragma unroll
    for (int w = 0; w < 8; w++) { suma += s1[w]; sumq += s2[w]; }
    float mean = suma * (1.f / 256.f);
    float var  = sumq * (1.f / 256.f) - mean * mean;
    float inv  = rsqrtf(var + 1e-5f);
    out[base + tid] = (v - mean) * inv * gamma[tid] + beta[tid];
}

// ---------------------------------------------------------------------------
// tf32 tensor-core GEMM: C = A @ W^T (+bias, +mode epilogue)
// 128x128 block tile, BK=32, 256 threads (8 warps, 32x64 warp tiles).
// ---------------------------------------------------------------------------
enum { M_QKV = 0, M_PROJ = 1, M_FC2 = 2, M_FC1 = 3 };

template <int MODE, int K>
__global__ __launch_bounds__(256) void gemm_tc(
    const float* __restrict__ Wt,
    const float* __restrict__ bias,
    const float* __restrict__ ext_in,
    float* __restrict__ ext_out)
{
    __shared__ __align__(16) float As[128][36];
    __shared__ __align__(16) float Bs[128][36];
    const int tid = threadIdx.x, lane = tid & 31, warp = tid >> 5;
    const int wm = warp >> 1, wn = warp & 1;
    const int g = lane >> 2, tg = lane & 3;
    const int m0 = blockIdx.x * 128, n0 = blockIdx.y * 128;

    const float* Abase =
        (MODE == M_PROJ) ? g_ao :
        (MODE == M_FC1)  ? g_z  :
        (MODE == M_FC2)  ? g_g  : (const float*)0;

    float c[2][8][4];
    #pragma unroll
    for (int mi = 0; mi < 2; mi++)
        #pragma unroll
        for (int ni = 0; ni < 8; ni++)
            #pragma unroll
            for (int k = 0; k < 4; k++) c[mi][ni][k] = 0.f;

    const int lm = tid >> 3, lq = tid & 7;
    for (int k0 = 0; k0 < K; k0 += 32) {
        #pragma unroll
        for (int i = 0; i < 4; i++) {
            int m = lm + 32 * i;
            const float* ap;
            if (MODE == M_QKV) ap = g_xn + spatial_idx(m0 + m) + k0 + lq * 4;
            else               ap = Abase + (size_t)(m0 + m) * K + k0 + lq * 4;
            float4 va = *(const float4*)ap;
            float4 ca = make_float4(to_tf32(va.x), to_tf32(va.y),
                                    to_tf32(va.z), to_tf32(va.w));
            *(float4*)&As[m][lq * 4] = ca;
            float4 vb = *(const float4*)(Wt + (size_t)(n0 + m) * K + k0 + lq * 4);
            float4 cb = make_float4(to_tf32(vb.x), to_tf32(vb.y),
                                    to_tf32(vb.z), to_tf32(vb.w));
            *(float4*)&Bs[m][lq * 4] = cb;
        }
        __syncthreads();
        #pragma unroll
        for (int kk = 0; kk < 32; kk += 8) {
            uint32_t a[2][4];
            #pragma unroll
            for (int mi = 0; mi < 2; mi++) {
                int r = wm * 32 + mi * 16;
                a[mi][0] = __float_as_uint(As[r + g][kk + tg]);
                a[mi][1] = __float_as_uint(As[r + 8 + g][kk + tg]);
                a[mi][2] = __float_as_uint(As[r + g][kk + 4 + tg]);
                a[mi][3] = __float_as_uint(As[r + 8 + g][kk + 4 + tg]);
            }
            #pragma unroll
            for (int ni = 0; ni < 8; ni++) {
                int cb = wn * 64 + ni * 8;
                uint32_t b0 = __float_as_uint(Bs[cb + g][kk + tg]);
                uint32_t b1 = __float_as_uint(Bs[cb + g][kk + 4 + tg]);
                mma8(c[0][ni], a[0], b0, b1);
                mma8(c[1][ni], a[1], b0, b1);
            }
        }
        __syncthreads();
    }

    #pragma unroll
    for (int mi = 0; mi < 2; mi++) {
        int rr0 = m0 + wm * 32 + mi * 16 + g;
        int rr1 = rr0 + 8;
        size_t sp0 = 0, sp1 = 0;
        if (MODE == M_PROJ) { sp0 = spatial_idx(rr0); sp1 = spatial_idx(rr1); }
        #pragma unroll
        for (int ni = 0; ni < 8; ni++) {
            int col = n0 + wn * 64 + ni * 8 + 2 * tg;
            float2 bb = *(const float2*)(bias + col);
            float v00 = c[mi][ni][0] + bb.x, v01 = c[mi][ni][1] + bb.y;
            float v10 = c[mi][ni][2] + bb.x, v11 = c[mi][ni][3] + bb.y;
            if (MODE == M_QKV) {
                *(float2*)&g_qkv[(size_t)rr0 * 384 + col] = make_float2(v00, v01);
                *(float2*)&g_qkv[(size_t)rr1 * 384 + col] = make_float2(v10, v11);
            } else if (MODE == M_PROJ) {
                size_t i0 = sp0 + col, i1 = sp1 + col;
                float2 s0 = *(const float2*)(ext_in + i0);
                float2 s1 = *(const float2*)(ext_in + i1);
                *(float2*)&g_y[i0] = make_float2(s0.x + v00, s0.y + v01);
                *(float2*)&g_y[i1] = make_float2(s1.x + v10, s1.y + v11);
            } else if (MODE == M_FC1) {
                *(float2*)&g_t[(size_t)rr0 * 512 + col] = make_float2(v00, v01);
                *(float2*)&g_t[(size_t)rr1 * 512 + col] = make_float2(v10, v11);
            } else { // M_FC2
                size_t i0 = (size_t)rr0 * 256 + col, i1 = (size_t)rr1 * 256 + col;
                float2 y0 = *(const float2*)&g_y[i0];
                float2 y1 = *(const float2*)&g_y[i1];
                *(float2*)&ext_out[i0] = make_float2(y0.x + v00, y0.y + v01);
                *(float2*)&ext_out[i1] = make_float2(y1.x + v10, y1.y + v11);
            }
        }
    }
}

// ---------------------------------------------------------------------------
// Grad scores + V transpose. One block per (p,b,win) = 4096 blocks.
// ---------------------------------------------------------------------------
__global__ __launch_bounds__(256) void gradv_kernel() {
    __shared__ float buf[64][130];
    int blk = blockIdx.x;
    int pb  = blk >> 8;
    int win = blk & 255;
    const float* qkv = g_qkv + (size_t)blk * 64 * 384;
    int tid = threadIdx.x;

    #pragma unroll
    for (int phase = 0; phase < 2; phase++) {
        for (int idx = tid; idx < 64*128; idx += 256)
            buf[idx >> 7][idx & 127] = qkv[(size_t)(idx >> 7) * 384 + phase*128 + (idx & 127)];
        __syncthreads();
        if (tid < 128) {
            float s = 0.f;
            #pragma unroll
            for (int tr = 0; tr < 8; tr++)
                #pragma unroll
                for (int tc = 0; tc < 8; tc++) {
                    float v = buf[tr*8+tc][tid];
                    float l = tc ? buf[tr*8+tc-1][tid] : 0.f;
                    float u = tr ? buf[(tr-1)*8+tc][tid] : 0.f;
                    s += fabsf(v - l) + fabsf(v - u);
                }
            size_t o = ((size_t)pb * 128 + tid) * 256 + win;
            if (phase == 0) g_qg[o] = s * QSCALE;
            else            g_kg[o] = s;
        }
        __syncthreads();
    }
    for (int idx = tid; idx < 64*128; idx += 256)
        buf[idx >> 7][idx & 127] = qkv[(size_t)(idx >> 7) * 384 + 256 + (idx & 127)];
    __syncthreads();
    for (int idx = tid; idx < 64*128; idx += 256) {
        int c = idx >> 6, t = idx & 63;
        g_vt[(((size_t)pb * 128 + c) * 256 + win) * 64 + t] = buf[t][c];
    }
}

// ---------------------------------------------------------------------------
// Tensor-core attention: per (p,b,c) block computes O = softmax(qg kg^T) V.
// M=256 (windows i), N=64 (tokens), K=256 (windows j), K-chunked by 32.
// A = exp weights built on the fly (qg,kg >= 0 so row max = qg_i * kmax).
// ---------------------------------------------------------------------------
__global__ __launch_bounds__(256) void attn_tc() {
    __shared__ float kg_s[256];
    __shared__ __align__(16) float Ws[256][37];
    __shared__ __align__(16) float Vst[64][36];
    int blk = blockIdx.x;
    int c  = blk & 127;
    int pb = blk >> 7;
    int tid = threadIdx.x, lane = tid & 31, warp = tid >> 5;
    int g = lane >> 2, tg = lane & 3;
    const float* kg = g_kg + (size_t)blk * 256;
    const float* qg = g_qg + (size_t)blk * 256;
    const float* v  = g_vt + (size_t)blk * (256 * 64);

    kg_s[tid] = kg[tid];
    __syncthreads();
    float kmax = -1e30f;
    for (int j = 0; j < 256; j++) kmax = fmaxf(kmax, kg_s[j]);
    float qgi = qg[tid];
    float m = qgi * kmax;      // qg,kg are sums of abs -> nonnegative
    float Zt = 0.f;

    float acc[2][8][4];
    #pragma unroll
    for (int mi = 0; mi < 2; mi++)
        #pragma unroll
        for (int ni = 0; ni < 8; ni++)
            #pragma unroll
            for (int k = 0; k < 4; k++) acc[mi][ni][k] = 0.f;

    for (int kc = 0; kc < 256; kc += 32) {
        #pragma unroll
        for (int jj = 0; jj < 32; jj++) {
            float w = __expf(fmaf(qgi, kg_s[kc + jj], -m));
            Zt += w;
            Ws[tid][jj] = to_tf32(w);
        }
        #pragma unroll
        for (int e = 0; e < 8; e++) {
            int l = e * 256 + tid;
            int j = l >> 6, t = l & 63;
            Vst[t][j] = to_tf32(v[(size_t)(kc + j) * 64 + t]);
        }
        __syncthreads();
        #pragma unroll
        for (int kk = 0; kk < 32; kk += 8) {
            uint32_t a[2][4];
            #pragma unroll
            for (int mi = 0; mi < 2; mi++) {
                int r = warp * 32 + mi * 16;
                a[mi][0] = __float_as_uint(Ws[r + g][kk + tg]);
                a[mi][1] = __float_as_uint(Ws[r + 8 + g][kk + tg]);
                a[mi][2] = __float_as_uint(Ws[r + g][kk + 4 + tg]);
                a[mi][3] = __float_as_uint(Ws[r + 8 + g][kk + 4 + tg]);
            }
            #pragma unroll
            for (int ni = 0; ni < 8; ni++) {
                uint32_t b0 = __float_as_uint(Vst[ni * 8 + g][kk + tg]);
                uint32_t b1 = __float_as_uint(Vst[ni * 8 + g][kk + 4 + tg]);
                mma8(acc[0][ni], a[0], b0, b1);
                mma8(acc[1][ni], a[1], b0, b1);
            }
        }
        __syncthreads();
    }

    kg_s[tid] = Zt;            // reuse as Z storage
    __syncthreads();
    #pragma unroll
    for (int mi = 0; mi < 2; mi++) {
        int r0 = warp * 32 + mi * 16 + g;
        int r1 = r0 + 8;
        float iz0 = 1.f / kg_s[r0];
        float iz1 = 1.f / kg_s[r1];
        size_t ob0 = (((size_t)pb * 256 + r0) * 64) * 128 + c;
        size_t ob1 = (((size_t)pb * 256 + r1) * 64) * 128 + c;
        #pragma unroll
        for (int ni = 0; ni < 8; ni++) {
            int t = ni * 8 + 2 * tg;
            g_ao[ob0 + (size_t)t * 128]       = acc[mi][ni][0] * iz0;
            g_ao[ob0 + (size_t)(t + 1) * 128] = acc[mi][ni][1] * iz0;
            g_ao[ob1 + (size_t)t * 128]       = acc[mi][ni][2] * iz1;
            g_ao[ob1 + (size_t)(t + 1) * 128] = acc[mi][ni][3] * iz1;
        }
    }
}

// ---------------------------------------------------------------------------
// Depthwise 3x3 + gate
// ---------------------------------------------------------------------------
__global__ __launch_bounds__(256) void gate_kernel(
    const float* __restrict__ dww, const float* __restrict__ dwb)
{
    int bh = blockIdx.x;
    int b  = bh >> 7;
    int hh = bh & 127;
    int c  = threadIdx.x;
    float w1[9], w2[9];
    #pragma unroll
    for (int k = 0; k < 9; k++) {
        w1[k] = dww[c*9 + k];
        w2[k] = dww[(c+256)*9 + k];
    }
    float b1 = dwb[c], b2 = dwb[c+256];
    const float* tb = g_t + (size_t)b * 16384 * 512;
    for (int ww = 0; ww < 128; ww++) {
        float s1 = b1, s2 = b2;
        #pragma unroll
        for (int dy = -1; dy <= 1; dy++) {
            int hy = hh + dy;
            if ((unsigned)hy < 128u) {
                #pragma unroll
                for (int dx = -1; dx <= 1; dx++) {
                    int wx = ww + dx;
                    if ((unsigned)wx < 128u) {
                        size_t off = ((size_t)hy * 128 + wx) * 512;
                        int kk = (dy+1)*3 + (dx+1);
                        s1 = fmaf(w1[kk], tb[off + c],       s1);
                        s2 = fmaf(w2[kk], tb[off + 256 + c], s2);
                    }
                }
            }
        }
        g_g[((size_t)b * 16384 + hh * 128 + ww) * 256 + c] = s1 * s2;
    }
}

// ---------------------------------------------------------------------------
// Launch
// ---------------------------------------------------------------------------
extern "C" void kernel_launch(void* const* d_in, const int* in_sizes, int n_in,
                              void* d_out, int out_size) {
    (void)in_sizes; (void)n_in; (void)out_size;
    const float* x     = (const float*)d_in[0];
    const float* n1g   = (const float*)d_in[1];
    const float* n1b   = (const float*)d_in[2];
    const float* qkvw  = (const float*)d_in[3];
    const float* qkvb  = (const float*)d_in[4];
    const float* projw = (const float*)d_in[5];
    const float* projb = (const float*)d_in[6];
    const float* n2g   = (const float*)d_in[7];
    const float* n2b   = (const float*)d_in[8];
    const float* fc1w  = (const float*)d_in[9];
    const float* fc1b  = (const float*)d_in[10];
    const float* dww   = (const float*)d_in[11];
    const float* dwb   = (const float*)d_in[12];
    const float* fc2w  = (const float*)d_in[13];
    const float* fc2b  = (const float*)d_in[14];
    float* out = (float*)d_out;

    ln_kernel<0><<<LTOT, 256>>>(x, n1g, n1b);
    gemm_tc<M_QKV, 128><<<dim3(QKV_ROWS/128, 3), 256>>>(qkvw, qkvb, (const float*)0, (float*)0);
    gradv_kernel<<<2*BATCH*NWIN, 256>>>();
    attn_tc<<<2*BATCH*128, 256>>>();
    gemm_tc<M_PROJ, 128><<<dim3(QKV_ROWS/128, 1), 256>>>(projw, projb, x, (float*)0);
    ln_kernel<1><<<LTOT, 256>>>((const float*)0, n2g, n2b);
    gemm_tc<M_FC1, 256><<<dim3(LTOT/128, 4), 256>>>(fc1w, fc1b, (const float*)0, (float*)0);
    gate_kernel<<<BATCH*HWD, 256>>>(dww, dwb);
    gemm_tc<M_FC2, 256><<<dim3(LTOT/128, 2), 256>>>(fc2w, fc2b, (const float*)0, out);
}

// round 5
// speedup vs baseline: 2.0764x; 1.0560x over previous
#include <cuda_runtime.h>
#include <math.h>
#include <stdint.h>

// ---------------------------------------------------------------------------
// Problem constants
// ---------------------------------------------------------------------------
namespace {
constexpr int BATCH = 8;
constexpr int HWD   = 128;
constexpr int DIM   = 256;
constexpr int NWIN  = 256;
constexpr int NTOK  = 64;
constexpr int LTOT  = BATCH * HWD * HWD;            // 131072
constexpr int QKV_ROWS = 2 * BATCH * NWIN * NTOK;   // 262144
constexpr int HID   = 512;
}
#define QSCALE  0.17677669529663687f   /* 32^-0.5 */
#define LOG2E   1.4426950408889634f

// ---------------------------------------------------------------------------
// Scratch (device globals)
// ---------------------------------------------------------------------------
__device__ float g_xn [(size_t)LTOT * DIM];
__device__ float g_qk [(size_t)QKV_ROWS * 256];      // Q,K only (V goes to g_vt)
__device__ float g_qg [(size_t)2*8*128*256];
__device__ float g_kg [(size_t)2*8*128*256];
__device__ float g_vt [(size_t)2*8*128*256*64];      // (p,b,c,win,tok)
__device__ float g_ao [(size_t)QKV_ROWS * 128];
__device__ float g_y  [(size_t)LTOT * DIM];
__device__ float g_z  [(size_t)LTOT * DIM];
__device__ float g_t  [(size_t)LTOT * HID];
__device__ float g_g  [(size_t)LTOT * DIM];

// ---------------------------------------------------------------------------
// Window row -> spatial index (roll handled; self-inverse map)
// ---------------------------------------------------------------------------
__device__ __forceinline__ size_t spatial_idx(int r) {
    int p   = r >> 17;
    int rem = r & 131071;
    int b   = rem >> 14;
    int win = (rem >> 6) & 255;
    int t   = rem & 63;
    int hh  = ((win >> 4) << 3) + (t >> 3);
    int ww  = ((win & 15) << 3) + (t & 7);
    if (p) { hh = (hh + 4) & 127; ww = (ww + 4) & 127; }
    return ((size_t)(b * 16384 + hh * 128 + ww)) * 256 + p * 128;
}

// ---------------------------------------------------------------------------
// tf32 MMA (HW truncates f32 operands to tf32; no explicit cvt needed)
// ---------------------------------------------------------------------------
__device__ __forceinline__ void mma8(float* c, const uint32_t* a,
                                     uint32_t b0, uint32_t b1) {
    asm volatile(
        "mma.sync.aligned.m16n8k8.row.col.f32.tf32.tf32.f32 "
        "{%0,%1,%2,%3},{%4,%5,%6,%7},{%8,%9},{%0,%1,%2,%3};"
        : "+f"(c[0]), "+f"(c[1]), "+f"(c[2]), "+f"(c[3])
        : "r"(a[0]), "r"(a[1]), "r"(a[2]), "r"(a[3]), "r"(b0), "r"(b1));
}

// ---------------------------------------------------------------------------
// LayerNorm
// ---------------------------------------------------------------------------
template <int MODE>
__global__ __launch_bounds__(256) void ln_kernel(
    const float* __restrict__ in_ext,
    const float* __restrict__ gamma, const float* __restrict__ beta)
{
    __shared__ float s1[8], s2[8];
    const float* in = (MODE == 0) ? in_ext : g_y;
    float* out      = (MODE == 0) ? g_xn  : g_z;
    size_t base = (size_t)blockIdx.x * 256;
    int tid = threadIdx.x;
    float v = in[base + tid];
    float a = v, q = v * v;
    #pragma unroll
    for (int o = 16; o > 0; o >>= 1) {
        a += __shfl_xor_sync(0xffffffffu, a, o);
        q += __shfl_xor_sync(0xffffffffu, q, o);
    }
    if ((tid & 31) == 0) { s1[tid >> 5] = a; s2[tid >> 5] = q; }
    __syncthreads();
    float suma = 0.f, sumq = 0.f;
    #pragma unroll
    for (int w = 0; w < 8; w++) { suma += s1[w]; sumq += s2[w]; }
    float mean = suma * (1.f / 256.f);
    float var  = sumq * (1.f / 256.f) - mean * mean;
    float inv  = rsqrtf(var + 1e-5f);
    out[base + tid] = (v - mean) * inv * gamma[tid] + beta[tid];
}

// ---------------------------------------------------------------------------
// tf32 tensor-core GEMM with register-prefetch double buffering.
// C = A @ W^T (+bias, +mode epilogue). 128x128 tile, BK=32, 256 threads.
// QKV mode: n-tiles 0,1 -> g_qk (Q,K); n-tile 2 -> g_vt (V, transposed scatter)
// ---------------------------------------------------------------------------
enum { M_QKV = 0, M_PROJ = 1, M_FC2 = 2, M_FC1 = 3 };

template <int MODE, int K>
__global__ __launch_bounds__(256) void gemm_tc(
    const float* __restrict__ Wt,
    const float* __restrict__ bias,
    const float* __restrict__ ext_in,
    float* __restrict__ ext_out)
{
    __shared__ __align__(16) float As[128][36];
    __shared__ __align__(16) float Bs[128][36];
    const int tid = threadIdx.x, lane = tid & 31, warp = tid >> 5;
    const int wm = warp >> 1, wn = warp & 1;
    const int g = lane >> 2, tg = lane & 3;
    const int m0 = blockIdx.x * 128, n0 = blockIdx.y * 128;

    const float* Abase =
        (MODE == M_PROJ) ? g_ao :
        (MODE == M_FC1)  ? g_z  :
        (MODE == M_FC2)  ? g_g  : (const float*)0;

    float c[2][8][4];
    #pragma unroll
    for (int mi = 0; mi < 2; mi++)
        #pragma unroll
        for (int ni = 0; ni < 8; ni++)
            #pragma unroll
            for (int k = 0; k < 4; k++) c[mi][ni][k] = 0.f;

    const int lm = tid >> 3, lq = tid & 7;
    // Per-thread row base pointers (fixed across k0)
    const float* arow[4];
    const float* brow[4];
    #pragma unroll
    for (int i = 0; i < 4; i++) {
        int m = lm + 32 * i;
        arow[i] = (MODE == M_QKV) ? (g_xn + spatial_idx(m0 + m))
                                  : (Abase + (size_t)(m0 + m) * K);
        brow[i] = Wt + (size_t)(n0 + m) * K;
    }

    float4 pa[4], pbf[4];
    #pragma unroll
    for (int i = 0; i < 4; i++) {
        pa[i]  = *(const float4*)(arow[i] + lq * 4);
        pbf[i] = *(const float4*)(brow[i] + lq * 4);
    }

    for (int k0 = 0; k0 < K; k0 += 32) {
        #pragma unroll
        for (int i = 0; i < 4; i++) {
            int m = lm + 32 * i;
            *(float4*)&As[m][lq * 4] = pa[i];
            *(float4*)&Bs[m][lq * 4] = pbf[i];
        }
        __syncthreads();
        if (k0 + 32 < K) {
            #pragma unroll
            for (int i = 0; i < 4; i++) {
                pa[i]  = *(const float4*)(arow[i] + k0 + 32 + lq * 4);
                pbf[i] = *(const float4*)(brow[i] + k0 + 32 + lq * 4);
            }
        }
        #pragma unroll
        for (int kk = 0; kk < 32; kk += 8) {
            uint32_t a[2][4];
            #pragma unroll
            for (int mi = 0; mi < 2; mi++) {
                int r = wm * 32 + mi * 16;
                a[mi][0] = __float_as_uint(As[r + g][kk + tg]);
                a[mi][1] = __float_as_uint(As[r + 8 + g][kk + tg]);
                a[mi][2] = __float_as_uint(As[r + g][kk + 4 + tg]);
                a[mi][3] = __float_as_uint(As[r + 8 + g][kk + 4 + tg]);
            }
            #pragma unroll
            for (int ni = 0; ni < 8; ni++) {
                int cb = wn * 64 + ni * 8;
                uint32_t b0 = __float_as_uint(Bs[cb + g][kk + tg]);
                uint32_t b1 = __float_as_uint(Bs[cb + g][kk + 4 + tg]);
                mma8(c[0][ni], a[0], b0, b1);
                mma8(c[1][ni], a[1], b0, b1);
            }
        }
        __syncthreads();
    }

    #pragma unroll
    for (int mi = 0; mi < 2; mi++) {
        int rr0 = m0 + wm * 32 + mi * 16 + g;
        int rr1 = rr0 + 8;
        size_t sp0 = 0, sp1 = 0;
        if (MODE == M_PROJ) { sp0 = spatial_idx(rr0); sp1 = spatial_idx(rr1); }
        // V scatter bases (QKV n-tile 2)
        size_t vb0 = 0, vb1 = 0;
        if (MODE == M_QKV && n0 == 256) {
            int pb0 = rr0 >> 14, w0 = (rr0 >> 6) & 255, t0 = rr0 & 63;
            int pb1 = rr1 >> 14, w1 = (rr1 >> 6) & 255, t1 = rr1 & 63;
            vb0 = (((size_t)pb0 * 128) * 256 + w0) * 64 + t0;
            vb1 = (((size_t)pb1 * 128) * 256 + w1) * 64 + t1;
        }
        #pragma unroll
        for (int ni = 0; ni < 8; ni++) {
            int col = n0 + wn * 64 + ni * 8 + 2 * tg;
            float2 bb = *(const float2*)(bias + col);
            float v00 = c[mi][ni][0] + bb.x, v01 = c[mi][ni][1] + bb.y;
            float v10 = c[mi][ni][2] + bb.x, v11 = c[mi][ni][3] + bb.y;
            if (MODE == M_QKV) {
                if (n0 < 256) {
                    *(float2*)&g_qk[(size_t)rr0 * 256 + col] = make_float2(v00, v01);
                    *(float2*)&g_qk[(size_t)rr1 * 256 + col] = make_float2(v10, v11);
                } else {
                    size_t cv = (size_t)(col - 256) * 16384;   // c stride in g_vt
                    g_vt[vb0 + cv]         = v00;
                    g_vt[vb0 + cv + 16384] = v01;
                    g_vt[vb1 + cv]         = v10;
                    g_vt[vb1 + cv + 16384] = v11;
                }
            } else if (MODE == M_PROJ) {
                size_t i0 = sp0 + col, i1 = sp1 + col;
                float2 s0 = *(const float2*)(ext_in + i0);
                float2 s1 = *(const float2*)(ext_in + i1);
                *(float2*)&g_y[i0] = make_float2(s0.x + v00, s0.y + v01);
                *(float2*)&g_y[i1] = make_float2(s1.x + v10, s1.y + v11);
            } else if (MODE == M_FC1) {
                *(float2*)&g_t[(size_t)rr0 * 512 + col] = make_float2(v00, v01);
                *(float2*)&g_t[(size_t)rr1 * 512 + col] = make_float2(v10, v11);
            } else { // M_FC2
                size_t i0 = (size_t)rr0 * 256 + col, i1 = (size_t)rr1 * 256 + col;
                float2 y0 = *(const float2*)&g_y[i0];
                float2 y1 = *(const float2*)&g_y[i1];
                *(float2*)&ext_out[i0] = make_float2(y0.x + v00, y0.y + v01);
                *(float2*)&ext_out[i1] = make_float2(y1.x + v10, y1.y + v11);
            }
        }
    }
}

// ---------------------------------------------------------------------------
// Grad scores (Q,K only now). One block per (p,b,win) = 4096 blocks.
// ---------------------------------------------------------------------------
__global__ __launch_bounds__(256) void gradv_kernel() {
    __shared__ float buf[64][130];
    int blk = blockIdx.x;
    int pb  = blk >> 8;
    int win = blk & 255;
    const float* qk = g_qk + (size_t)blk * 64 * 256;
    int tid = threadIdx.x;

    #pragma unroll
    for (int phase = 0; phase < 2; phase++) {
        for (int idx = tid; idx < 64*128; idx += 256)
            buf[idx >> 7][idx & 127] = qk[(size_t)(idx >> 7) * 256 + phase*128 + (idx & 127)];
        __syncthreads();
        if (tid < 128) {
            float s = 0.f;
            #pragma unroll
            for (int tr = 0; tr < 8; tr++)
                #pragma unroll
                for (int tc = 0; tc < 8; tc++) {
                    float v = buf[tr*8+tc][tid];
                    float l = tc ? buf[tr*8+tc-1][tid] : 0.f;
                    float u = tr ? buf[(tr-1)*8+tc][tid] : 0.f;
                    s += fabsf(v - l) + fabsf(v - u);
                }
            size_t o = ((size_t)pb * 128 + tid) * 256 + win;
            if (phase == 0) g_qg[o] = s * QSCALE;
            else            g_kg[o] = s;
        }
        __syncthreads();
    }
}

// ---------------------------------------------------------------------------
// Tensor-core attention, M-tile = 128 for occupancy.
// Grid = 4096: block = (pb,c) x m-half.  O = softmax(qg kg^T) V per channel.
// ---------------------------------------------------------------------------
__global__ __launch_bounds__(256) void attn_tc() {
    __shared__ float kg_s[256];
    __shared__ float red[8];
    __shared__ float zrow[128];
    __shared__ __align__(16) float Ws[128][36];
    __shared__ __align__(16) float Vst[64][36];
    int bx = blockIdx.x;
    int mhalf = bx & 1;
    int blk = bx >> 1;
    int c  = blk & 127;
    int pb = blk >> 7;
    int tid = threadIdx.x, lane = tid & 31, warp = tid >> 5;
    int g = lane >> 2, tg = lane & 3;
    const float* kg = g_kg + (size_t)blk * 256;
    const float* qg = g_qg + (size_t)blk * 256;
    const float* v  = g_vt + (size_t)blk * (256 * 64);

    // load kg + block-wide max
    float kv = kg[tid];
    kg_s[tid] = kv;
    float km = kv;
    #pragma unroll
    for (int o = 16; o > 0; o >>= 1)
        km = fmaxf(km, __shfl_xor_sync(0xffffffffu, km, o));
    if (lane == 0) red[warp] = km;
    __syncthreads();
    km = red[0];
    #pragma unroll
    for (int w = 1; w < 8; w++) km = fmaxf(km, red[w]);

    // exp-row assignment: thread pair (2 threads) per row
    int erow  = tid >> 1;            // 0..127 (local i)
    int ehalf = tid & 1;             // j half within 32-chunk
    float qg2 = qg[mhalf * 128 + erow] * LOG2E;
    float m2  = qg2 * km;            // qg,kg nonnegative
    float zacc = 0.f;

    float acc[8][4];
    #pragma unroll
    for (int ni = 0; ni < 8; ni++)
        #pragma unroll
        for (int k = 0; k < 4; k++) acc[ni][k] = 0.f;

    for (int kc = 0; kc < 256; kc += 32) {
        #pragma unroll
        for (int q = 0; q < 16; q++) {
            int j = ehalf * 16 + q;
            float w = exp2f(fmaf(qg2, kg_s[kc + j], -m2));
            zacc += w;
            Ws[erow][j] = w;
        }
        #pragma unroll
        for (int e = 0; e < 8; e++) {
            int l = e * 256 + tid;
            int j = l >> 6, t = l & 63;
            Vst[t][j] = v[(size_t)(kc + j) * 64 + t];
        }
        __syncthreads();
        #pragma unroll
        for (int kk = 0; kk < 32; kk += 8) {
            uint32_t a[4];
            int r = warp * 16;
            a[0] = __float_as_uint(Ws[r + g][kk + tg]);
            a[1] = __float_as_uint(Ws[r + 8 + g][kk + tg]);
            a[2] = __float_as_uint(Ws[r + g][kk + 4 + tg]);
            a[3] = __float_as_uint(Ws[r + 8 + g][kk + 4 + tg]);
            #pragma unroll
            for (int ni = 0; ni < 8; ni++) {
                uint32_t b0 = __float_as_uint(Vst[ni * 8 + g][kk + tg]);
                uint32_t b1 = __float_as_uint(Vst[ni * 8 + g][kk + 4 + tg]);
                mma8(acc[ni], a, b0, b1);
            }
        }
        __syncthreads();
    }

    // Z per row (pair-sum), then normalize + store
    zacc += __shfl_xor_sync(0xffffffffu, zacc, 1);
    if (ehalf == 0) zrow[erow] = zacc;
    __syncthreads();

    int r0l = warp * 16 + g, r1l = r0l + 8;
    float iz0 = 1.f / zrow[r0l];
    float iz1 = 1.f / zrow[r1l];
    int i0 = mhalf * 128 + r0l, i1 = mhalf * 128 + r1l;
    size_t ob0 = (((size_t)pb * 256 + i0) * 64) * 128 + c;
    size_t ob1 = (((size_t)pb * 256 + i1) * 64) * 128 + c;
    #pragma unroll
    for (int ni = 0; ni < 8; ni++) {
        int t = ni * 8 + 2 * tg;
        g_ao[ob0 + (size_t)t * 128]       = acc[ni][0] * iz0;
        g_ao[ob0 + (size_t)(t + 1) * 128] = acc[ni][1] * iz0;
        g_ao[ob1 + (size_t)t * 128]       = acc[ni][2] * iz1;
        g_ao[ob1 + (size_t)(t + 1) * 128] = acc[ni][3] * iz1;
    }
}

// ---------------------------------------------------------------------------
// Depthwise 3x3 + gate
// ---------------------------------------------------------------------------
__global__ __launch_bounds__(256) void gate_kernel(
    const float* __restrict__ dww, const float* __restrict__ dwb)
{
    int bh = blockIdx.x;
    int b  = bh >> 7;
    int hh = bh & 127;
    int c  = threadIdx.x;
    float w1[9], w2[9];
    #pragma unroll
    for (int k = 0; k < 9; k++) {
        w1[k] = dww[c*9 + k];
        w2[k] = dww[(c+256)*9 + k];
    }
    float b1 = dwb[c], b2 = dwb[c+256];
    const float* tb = g_t + (size_t)b * 16384 * 512;
    for (int ww = 0; ww < 128; ww++) {
        float s1 = b1, s2 = b2;
        #pragma unroll
        for (int dy = -1; dy <= 1; dy++) {
            int hy = hh + dy;
            if ((unsigned)hy < 128u) {
                #pragma unroll
                for (int dx = -1; dx <= 1; dx++) {
                    int wx = ww + dx;
                    if ((unsigned)wx < 128u) {
                        size_t off = ((size_t)hy * 128 + wx) * 512;
                        int kk = (dy+1)*3 + (dx+1);
                        s1 = fmaf(w1[kk], tb[off + c],       s1);
                        s2 = fmaf(w2[kk], tb[off + 256 + c], s2);
                    }
                }
            }
        }
        g_g[((size_t)b * 16384 + hh * 128 + ww) * 256 + c] = s1 * s2;
    }
}

// ---------------------------------------------------------------------------
// Launch
// ---------------------------------------------------------------------------
extern "C" void kernel_launch(void* const* d_in, const int* in_sizes, int n_in,
                              void* d_out, int out_size) {
    (void)in_sizes; (void)n_in; (void)out_size;
    const float* x     = (const float*)d_in[0];
    const float* n1g   = (const float*)d_in[1];
    const float* n1b   = (const float*)d_in[2];
    const float* qkvw  = (const float*)d_in[3];
    const float* qkvb  = (const float*)d_in[4];
    const float* projw = (const float*)d_in[5];
    const float* projb = (const float*)d_in[6];
    const float* n2g   = (const float*)d_in[7];
    const float* n2b   = (const float*)d_in[8];
    const float* fc1w  = (const float*)d_in[9];
    const float* fc1b  = (const float*)d_in[10];
    const float* dww   = (const float*)d_in[11];
    const float* dwb   = (const float*)d_in[12];
    const float* fc2w  = (const float*)d_in[13];
    const float* fc2b  = (const float*)d_in[14];
    float* out = (float*)d_out;

    ln_kernel<0><<<LTOT, 256>>>(x, n1g, n1b);
    gemm_tc<M_QKV, 128><<<dim3(QKV_ROWS/128, 3), 256>>>(qkvw, qkvb, (const float*)0, (float*)0);
    gradv_kernel<<<2*BATCH*NWIN, 256>>>();
    attn_tc<<<2*BATCH*128*2, 256>>>();
    gemm_tc<M_PROJ, 128><<<dim3(QKV_ROWS/128, 1), 256>>>(projw, projb, x, (float*)0);
    ln_kernel<1><<<LTOT, 256>>>((const float*)0, n2g, n2b);
    gemm_tc<M_FC1, 256><<<dim3(LTOT/128, 4), 256>>>(fc1w, fc1b, (const float*)0, (float*)0);
    gate_kernel<<<BATCH*HWD, 256>>>(dww, dwb);
    gemm_tc<M_FC2, 256><<<dim3(LTOT/128, 2), 256>>>(fc2w, fc2b, (const float*)0, out);
}

// round 7
// speedup vs baseline: 2.3427x; 1.1283x over previous
#include <cuda_runtime.h>
#include <math.h>
#include <stdint.h>

// ---------------------------------------------------------------------------
// Problem constants
// ---------------------------------------------------------------------------
namespace {
constexpr int BATCH = 8;
constexpr int HWD   = 128;
constexpr int DIM   = 256;
constexpr int NWIN  = 256;
constexpr int NTOK  = 64;
constexpr int LTOT  = BATCH * HWD * HWD;            // 131072
constexpr int QKV_ROWS = 2 * BATCH * NWIN * NTOK;   // 262144
constexpr int HID   = 512;
constexpr int GEMM_SMEM = 2 * 2 * 128 * 36 * 4;     // 73728 B (As x2 + Bs x2)
constexpr int ATTN_SMEM = (400 + 2*4608 + 2*2304) * 4; // 56896 B
}
#define QSCALE  0.17677669529663687f   /* 32^-0.5 */
#define LOG2E   1.4426950408889634f

// ---------------------------------------------------------------------------
// Scratch (device globals)
// ---------------------------------------------------------------------------
__device__ float g_xn [(size_t)LTOT * DIM];
__device__ float g_qk [(size_t)QKV_ROWS * 256];      // Q,K only (V -> g_vt)
__device__ float g_qg [(size_t)2*8*128*256];
__device__ float g_kg [(size_t)2*8*128*256];
__device__ float g_vt [(size_t)2*8*128*256*64];      // (p,b,c,win,tok)
__device__ float g_ao [(size_t)QKV_ROWS * 128];
__device__ float g_y  [(size_t)LTOT * DIM];
__device__ float g_z  [(size_t)LTOT * DIM];
__device__ float g_t  [(size_t)LTOT * HID];
__device__ float g_g  [(size_t)LTOT * DIM];

// ---------------------------------------------------------------------------
// Window row -> spatial index (roll handled; self-inverse map)
// ---------------------------------------------------------------------------
__device__ __forceinline__ size_t spatial_idx(int r) {
    int p   = r >> 17;
    int rem = r & 131071;
    int b   = rem >> 14;
    int win = (rem >> 6) & 255;
    int t   = rem & 63;
    int hh  = ((win >> 4) << 3) + (t >> 3);
    int ww  = ((win & 15) << 3) + (t & 7);
    if (p) { hh = (hh + 4) & 127; ww = (ww + 4) & 127; }
    return ((size_t)(b * 16384 + hh * 128 + ww)) * 256 + p * 128;
}

// ---------------------------------------------------------------------------
// tf32 MMA (HW truncates f32 operands to tf32)
// ---------------------------------------------------------------------------
__device__ __forceinline__ void mma8(float* c, const uint32_t* a,
                                     uint32_t b0, uint32_t b1) {
    asm volatile(
        "mma.sync.aligned.m16n8k8.row.col.f32.tf32.tf32.f32 "
        "{%0,%1,%2,%3},{%4,%5,%6,%7},{%8,%9},{%0,%1,%2,%3};"
        : "+f"(c[0]), "+f"(c[1]), "+f"(c[2]), "+f"(c[3])
        : "r"(a[0]), "r"(a[1]), "r"(a[2]), "r"(a[3]), "r"(b0), "r"(b1));
}

// ---------------------------------------------------------------------------
// LayerNorm
// ---------------------------------------------------------------------------
template <int MODE>
__global__ __launch_bounds__(256) void ln_kernel(
    const float* __restrict__ in_ext,
    const float* __restrict__ gamma, const float* __restrict__ beta)
{
    __shared__ float s1[8], s2[8];
    const float* in = (MODE == 0) ? in_ext : g_y;
    float* out      = (MODE == 0) ? g_xn  : g_z;
    size_t base = (size_t)blockIdx.x * 256;
    int tid = threadIdx.x;
    float v = in[base + tid];
    float a = v, q = v * v;
    #pragma unroll
    for (int o = 16; o > 0; o >>= 1) {
        a += __shfl_xor_sync(0xffffffffu, a, o);
        q += __shfl_xor_sync(0xffffffffu, q, o);
    }
    if ((tid & 31) == 0) { s1[tid >> 5] = a; s2[tid >> 5] = q; }
    __syncthreads();
    float suma = 0.f, sumq = 0.f;
    #pragma unroll
    for (int w = 0; w < 8; w++) { suma += s1[w]; sumq += s2[w]; }
    float mean = suma * (1.f / 256.f);
    float var  = sumq * (1.f / 256.f) - mean * mean;
    float inv  = rsqrtf(var + 1e-5f);
    out[base + tid] = (v - mean) * inv * gamma[tid] + beta[tid];
}

// ---------------------------------------------------------------------------
// tf32 GEMM, double-buffered smem pipeline (1 bar per K-chunk).
// C = A @ W^T (+bias, +mode epilogue). 128x128 tile, BK=32, 256 threads.
// ---------------------------------------------------------------------------
enum { M_QKV = 0, M_PROJ = 1, M_FC2 = 2, M_FC1 = 3 };

#define ATS(b,m,k) dsm[(b)*4608 + (m)*36 + (k)]
#define BTS(b,m,k) dsm[9216 + (b)*4608 + (m)*36 + (k)]

template <int MODE, int K>
__global__ __launch_bounds__(256, 2) void gemm_tc(
    const float* __restrict__ Wt,
    const float* __restrict__ bias,
    const float* __restrict__ ext_in,
    float* __restrict__ ext_out)
{
    extern __shared__ float dsm[];
    const int tid = threadIdx.x, lane = tid & 31, warp = tid >> 5;
    const int wm = warp >> 1, wn = warp & 1;
    const int g = lane >> 2, tg = lane & 3;
    const int m0 = blockIdx.x * 128, n0 = blockIdx.y * 128;
    constexpr int NC = K / 32;

    const float* Abase =
        (MODE == M_PROJ) ? g_ao :
        (MODE == M_FC1)  ? g_z  :
        (MODE == M_FC2)  ? g_g  : (const float*)0;

    float c[2][8][4];
    #pragma unroll
    for (int mi = 0; mi < 2; mi++)
        #pragma unroll
        for (int ni = 0; ni < 8; ni++)
            #pragma unroll
            for (int k = 0; k < 4; k++) c[mi][ni][k] = 0.f;

    const int lm = tid >> 3, lq = tid & 7;
    const float* arow[4];
    const float* brow[4];
    #pragma unroll
    for (int i = 0; i < 4; i++) {
        int m = lm + 32 * i;
        arow[i] = (MODE == M_QKV) ? (g_xn + spatial_idx(m0 + m))
                                  : (Abase + (size_t)(m0 + m) * K);
        brow[i] = Wt + (size_t)(n0 + m) * K;
    }

    float4 pa[4], pbf[4];
    #pragma unroll
    for (int i = 0; i < 4; i++) {
        pa[i]  = *(const float4*)(arow[i] + lq * 4);
        pbf[i] = *(const float4*)(brow[i] + lq * 4);
    }
    #pragma unroll
    for (int i = 0; i < 4; i++) {
        int m = lm + 32 * i;
        *(float4*)&ATS(0, m, lq * 4) = pa[i];
        *(float4*)&BTS(0, m, lq * 4) = pbf[i];
    }
    __syncthreads();
    if (NC > 1) {
        #pragma unroll
        for (int i = 0; i < 4; i++) {
            pa[i]  = *(const float4*)(arow[i] + 32 + lq * 4);
            pbf[i] = *(const float4*)(brow[i] + 32 + lq * 4);
        }
    }

    for (int ic = 0; ic < NC; ic++) {
        int cur = ic & 1, nxt = cur ^ 1;
        if (ic < NC - 1) {
            #pragma unroll
            for (int i = 0; i < 4; i++) {
                int m = lm + 32 * i;
                *(float4*)&ATS(nxt, m, lq * 4) = pa[i];
                *(float4*)&BTS(nxt, m, lq * 4) = pbf[i];
            }
            if (ic < NC - 2) {
                int koff = (ic + 2) * 32 + lq * 4;
                #pragma unroll
                for (int i = 0; i < 4; i++) {
                    pa[i]  = *(const float4*)(arow[i] + koff);
                    pbf[i] = *(const float4*)(brow[i] + koff);
                }
            }
        }
        #pragma unroll
        for (int kk = 0; kk < 32; kk += 8) {
            uint32_t a[2][4];
            #pragma unroll
            for (int mi = 0; mi < 2; mi++) {
                int r = wm * 32 + mi * 16;
                a[mi][0] = __float_as_uint(ATS(cur, r + g,     kk + tg));
                a[mi][1] = __float_as_uint(ATS(cur, r + 8 + g, kk + tg));
                a[mi][2] = __float_as_uint(ATS(cur, r + g,     kk + 4 + tg));
                a[mi][3] = __float_as_uint(ATS(cur, r + 8 + g, kk + 4 + tg));
            }
            #pragma unroll
            for (int ni = 0; ni < 8; ni++) {
                int cb = wn * 64 + ni * 8;
                uint32_t b0 = __float_as_uint(BTS(cur, cb + g, kk + tg));
                uint32_t b1 = __float_as_uint(BTS(cur, cb + g, kk + 4 + tg));
                mma8(c[0][ni], a[0], b0, b1);
                mma8(c[1][ni], a[1], b0, b1);
            }
        }
        __syncthreads();
    }

    #pragma unroll
    for (int mi = 0; mi < 2; mi++) {
        int rr0 = m0 + wm * 32 + mi * 16 + g;
        int rr1 = rr0 + 8;
        size_t sp0 = 0, sp1 = 0;
        if (MODE == M_PROJ) { sp0 = spatial_idx(rr0); sp1 = spatial_idx(rr1); }
        size_t vb0 = 0, vb1 = 0;
        if (MODE == M_QKV && n0 == 256) {
            int pb0 = rr0 >> 14, w0 = (rr0 >> 6) & 255, t0 = rr0 & 63;
            int pb1 = rr1 >> 14, w1 = (rr1 >> 6) & 255, t1 = rr1 & 63;
            vb0 = (((size_t)pb0 * 128) * 256 + w0) * 64 + t0;
            vb1 = (((size_t)pb1 * 128) * 256 + w1) * 64 + t1;
        }
        #pragma unroll
        for (int ni = 0; ni < 8; ni++) {
            int col = n0 + wn * 64 + ni * 8 + 2 * tg;
            float2 bb = *(const float2*)(bias + col);
            float v00 = c[mi][ni][0] + bb.x, v01 = c[mi][ni][1] + bb.y;
            float v10 = c[mi][ni][2] + bb.x, v11 = c[mi][ni][3] + bb.y;
            if (MODE == M_QKV) {
                if (n0 < 256) {
                    *(float2*)&g_qk[(size_t)rr0 * 256 + col] = make_float2(v00, v01);
                    *(float2*)&g_qk[(size_t)rr1 * 256 + col] = make_float2(v10, v11);
                } else {
                    size_t cv = (size_t)(col - 256) * 16384;
                    g_vt[vb0 + cv]         = v00;
                    g_vt[vb0 + cv + 16384] = v01;
                    g_vt[vb1 + cv]         = v10;
                    g_vt[vb1 + cv + 16384] = v11;
                }
            } else if (MODE == M_PROJ) {
                size_t i0 = sp0 + col, i1 = sp1 + col;
                float2 s0 = *(const float2*)(ext_in + i0);
                float2 s1 = *(const float2*)(ext_in + i1);
                *(float2*)&g_y[i0] = make_float2(s0.x + v00, s0.y + v01);
                *(float2*)&g_y[i1] = make_float2(s1.x + v10, s1.y + v11);
            } else if (MODE == M_FC1) {
                *(float2*)&g_t[(size_t)rr0 * 512 + col] = make_float2(v00, v01);
                *(float2*)&g_t[(size_t)rr1 * 512 + col] = make_float2(v10, v11);
            } else { // M_FC2
                size_t i0 = (size_t)rr0 * 256 + col, i1 = (size_t)rr1 * 256 + col;
                float2 y0 = *(const float2*)&g_y[i0];
                float2 y1 = *(const float2*)&g_y[i1];
                *(float2*)&ext_out[i0] = make_float2(y0.x + v00, y0.y + v01);
                *(float2*)&ext_out[i1] = make_float2(y1.x + v10, y1.y + v11);
            }
        }
    }
}

// ---------------------------------------------------------------------------
// Grad scores (Q,K). One block per (p,b,win) = 4096 blocks.
// ---------------------------------------------------------------------------
__global__ __launch_bounds__(256) void gradv_kernel() {
    __shared__ float buf[64][130];
    int blk = blockIdx.x;
    int pb  = blk >> 8;
    int win = blk & 255;
    const float* qk = g_qk + (size_t)blk * 64 * 256;
    int tid = threadIdx.x;

    #pragma unroll
    for (int phase = 0; phase < 2; phase++) {
        for (int idx = tid; idx < 64*128; idx += 256)
            buf[idx >> 7][idx & 127] = qk[(size_t)(idx >> 7) * 256 + phase*128 + (idx & 127)];
        __syncthreads();
        if (tid < 128) {
            float s = 0.f;
            #pragma unroll
            for (int tr = 0; tr < 8; tr++)
                #pragma unroll
                for (int tc = 0; tc < 8; tc++) {
                    float v = buf[tr*8+tc][tid];
                    float l = tc ? buf[tr*8+tc-1][tid] : 0.f;
                    float u = tr ? buf[(tr-1)*8+tc][tid] : 0.f;
                    s += fabsf(v - l) + fabsf(v - u);
                }
            size_t o = ((size_t)pb * 128 + tid) * 256 + win;
            if (phase == 0) g_qg[o] = s * QSCALE;
            else            g_kg[o] = s;
        }
        __syncthreads();
    }
}

// ---------------------------------------------------------------------------
// Tensor-core attention, double-buffered (1 bar/chunk) + V register prefetch.
// Grid = 4096: block = (pb,c) x m-half.  O = softmax(qg kg^T) V per channel.
// dsm layout (floats): kg_s[256] | zrow[128] | red[8]+pad | Ws[2][128*36] | Vst[2][64*36]
// ---------------------------------------------------------------------------
#define WSM(b,r,j) dsm[400 + (b)*4608 + (r)*36 + (j)]
#define VSM(b,t,j) dsm[9616 + (b)*2304 + (t)*36 + (j)]

__global__ __launch_bounds__(256, 3) void attn_tc() {
    extern __shared__ float dsm[];
    float* kg_s = dsm;
    float* zrow = dsm + 256;
    float* red  = dsm + 384;
    int bx = blockIdx.x;
    int mhalf = bx & 1;
    int blk = bx >> 1;
    int c  = blk & 127;
    int pb = blk >> 7;
    int tid = threadIdx.x, lane = tid & 31, warp = tid >> 5;
    int g = lane >> 2, tg = lane & 3;
    const float* kg = g_kg + (size_t)blk * 256;
    const float* qg = g_qg + (size_t)blk * 256;
    const float* v  = g_vt + (size_t)blk * (256 * 64);

    // kg + block max
    float kv = kg[tid];
    kg_s[tid] = kv;
    float km = kv;
    #pragma unroll
    for (int o = 16; o > 0; o >>= 1)
        km = fmaxf(km, __shfl_xor_sync(0xffffffffu, km, o));
    if (lane == 0) red[warp] = km;
    __syncthreads();
    km = red[0];
    #pragma unroll
    for (int w = 1; w < 8; w++) km = fmaxf(km, red[w]);

    int erow  = tid >> 1;            // row within m-half
    int ehalf = tid & 1;
    const int vj = tid >> 6;         // V-load j sub-index
    const int vt = tid & 63;         // V-load token
    float qg2 = qg[mhalf * 128 + erow] * LOG2E;
    float m2  = qg2 * km;
    float zacc = 0.f;

    float acc[8][4];
    #pragma unroll
    for (int ni = 0; ni < 8; ni++)
        #pragma unroll
        for (int k = 0; k < 4; k++) acc[ni][k] = 0.f;

    // ---- prologue: chunk 0 into buffer 0
    #pragma unroll
    for (int q = 0; q < 16; q++) {
        int j = ehalf * 16 + q;
        float w = exp2f(fmaf(qg2, kg_s[j], -m2));
        zacc += w;
        WSM(0, erow, j) = w;
    }
    #pragma unroll
    for (int e = 0; e < 8; e++) {
        int j = e * 4 + vj;
        VSM(0, vt, j) = v[(size_t)j * 64 + vt];
    }
    __syncthreads();

    float vreg[8];
    #pragma unroll
    for (int e = 0; e < 8; e++) {
        int j = e * 4 + vj;
        vreg[e] = v[(size_t)(32 + j) * 64 + vt];
    }

    for (int ic = 0; ic < 8; ic++) {
        int cur = ic & 1, nxt = cur ^ 1;
        if (ic < 7) {
            #pragma unroll
            for (int e = 0; e < 8; e++)
                VSM(nxt, vt, e * 4 + vj) = vreg[e];
            if (ic < 6) {
                int kcv = (ic + 2) * 32;
                #pragma unroll
                for (int e = 0; e < 8; e++)
                    vreg[e] = v[(size_t)(kcv + e * 4 + vj) * 64 + vt];
            }
            int kcn = (ic + 1) * 32;
            #pragma unroll
            for (int q = 0; q < 16; q++) {
                int j = ehalf * 16 + q;
                float w = exp2f(fmaf(qg2, kg_s[kcn + j], -m2));
                zacc += w;
                WSM(nxt, erow, j) = w;
            }
        }
        #pragma unroll
        for (int kk = 0; kk < 32; kk += 8) {
            uint32_t a[4];
            int r = warp * 16;
            a[0] = __float_as_uint(WSM(cur, r + g,     kk + tg));
            a[1] = __float_as_uint(WSM(cur, r + 8 + g, kk + tg));
            a[2] = __float_as_uint(WSM(cur, r + g,     kk + 4 + tg));
            a[3] = __float_as_uint(WSM(cur, r + 8 + g, kk + 4 + tg));
            #pragma unroll
            for (int ni = 0; ni < 8; ni++) {
                uint32_t b0 = __float_as_uint(VSM(cur, ni * 8 + g, kk + tg));
                uint32_t b1 = __float_as_uint(VSM(cur, ni * 8 + g, kk + 4 + tg));
                mma8(acc[ni], a, b0, b1);
            }
        }
        __syncthreads();
    }

    // Z per row (pair-sum), normalize, store
    zacc += __shfl_xor_sync(0xffffffffu, zacc, 1);
    if (ehalf == 0) zrow[erow] = zacc;
    __syncthreads();

    int r0l = warp * 16 + g, r1l = r0l + 8;
    float iz0 = 1.f / zrow[r0l];
    float iz1 = 1.f / zrow[r1l];
    int i0 = mhalf * 128 + r0l, i1 = mhalf * 128 + r1l;
    size_t ob0 = (((size_t)pb * 256 + i0) * 64) * 128 + c;
    size_t ob1 = (((size_t)pb * 256 + i1) * 64) * 128 + c;
    #pragma unroll
    for (int ni = 0; ni < 8; ni++) {
        int t = ni * 8 + 2 * tg;
        g_ao[ob0 + (size_t)t * 128]       = acc[ni][0] * iz0;
        g_ao[ob0 + (size_t)(t + 1) * 128] = acc[ni][1] * iz0;
        g_ao[ob1 + (size_t)t * 128]       = acc[ni][2] * iz1;
        g_ao[ob1 + (size_t)(t + 1) * 128] = acc[ni][3] * iz1;
    }
}

// ---------------------------------------------------------------------------
// Depthwise 3x3 + gate, sliding-column register window (6 LDG/output)
// ---------------------------------------------------------------------------
__global__ __launch_bounds__(256) void gate_kernel(
    const float* __restrict__ dww, const float* __restrict__ dwb)
{
    int bh = blockIdx.x;
    int b  = bh >> 7;
    int hh = bh & 127;
    int c  = threadIdx.x;
    float w1[9], w2[9];
    #pragma unroll
    for (int k = 0; k < 9; k++) {
        w1[k] = dww[c*9 + k];
        w2[k] = dww[(c+256)*9 + k];
    }
    float b1 = dwb[c], b2 = dwb[c+256];
    const float* tb = g_t + (size_t)b * 16384 * 512;
    float* gout = g_g + ((size_t)b * 16384 + hh * 128) * 256 + c;

    float cA[3][3], cB[3][3];   // [colpos m/0/p][row]
    #pragma unroll
    for (int r = 0; r < 3; r++) { cA[0][r] = 0.f; cB[0][r] = 0.f; }
    #pragma unroll
    for (int r = 0; r < 3; r++) {
        int hy = hh - 1 + r;
        bool ok = (unsigned)hy < 128u;
        size_t off = ((size_t)hy * 128 + 0) * 512;
        cA[1][r] = ok ? tb[off + c]       : 0.f;
        cB[1][r] = ok ? tb[off + 256 + c] : 0.f;
        cA[2][r] = ok ? tb[off + 512 + c]       : 0.f;
        cB[2][r] = ok ? tb[off + 512 + 256 + c] : 0.f;
    }

    for (int ww = 0; ww < 128; ww++) {
        float s1 = b1, s2 = b2;
        #pragma unroll
        for (int r = 0; r < 3; r++) {
            s1 = fmaf(cA[0][r], w1[r*3+0], s1);
            s1 = fmaf(cA[1][r], w1[r*3+1], s1);
            s1 = fmaf(cA[2][r], w1[r*3+2], s1);
            s2 = fmaf(cB[0][r], w2[r*3+0], s2);
            s2 = fmaf(cB[1][r], w2[r*3+1], s2);
            s2 = fmaf(cB[2][r], w2[r*3+2], s2);
        }
        gout[(size_t)ww * 256] = s1 * s2;
        // shift window, load column ww+2
        int wx = ww + 2;
        bool okx = wx < 128;
        #pragma unroll
        for (int r = 0; r < 3; r++) {
            cA[0][r] = cA[1][r]; cA[1][r] = cA[2][r];
            cB[0][r] = cB[1][r]; cB[1][r] = cB[2][r];
            int hy = hh - 1 + r;
            bool ok = okx && (unsigned)hy < 128u;
            size_t off = ((size_t)hy * 128 + wx) * 512;
            cA[2][r] = ok ? tb[off + c]       : 0.f;
            cB[2][r] = ok ? tb[off + 256 + c] : 0.f;
        }
    }
}

// ---------------------------------------------------------------------------
// Launch.  cudaFuncSetAttribute is called unconditionally on every invocation
// (no static guards — harness requires identical behavior on every call; the
// attribute API is non-stream and capture-safe).
// ---------------------------------------------------------------------------
extern "C" void kernel_launch(void* const* d_in, const int* in_sizes, int n_in,
                              void* d_out, int out_size) {
    (void)in_sizes; (void)n_in; (void)out_size;
    const float* x     = (const float*)d_in[0];
    const float* n1g   = (const float*)d_in[1];
    const float* n1b   = (const float*)d_in[2];
    const float* qkvw  = (const float*)d_in[3];
    const float* qkvb  = (const float*)d_in[4];
    const float* projw = (const float*)d_in[5];
    const float* projb = (const float*)d_in[6];
    const float* n2g   = (const float*)d_in[7];
    const float* n2b   = (const float*)d_in[8];
    const float* fc1w  = (const float*)d_in[9];
    const float* fc1b  = (const float*)d_in[10];
    const float* dww   = (const float*)d_in[11];
    const float* dwb   = (const float*)d_in[12];
    const float* fc2w  = (const float*)d_in[13];
    const float* fc2b  = (const float*)d_in[14];
    float* out = (float*)d_out;

    cudaFuncSetAttribute(gemm_tc<M_QKV,128>,  cudaFuncAttributeMaxDynamicSharedMemorySize, GEMM_SMEM);
    cudaFuncSetAttribute(gemm_tc<M_PROJ,128>, cudaFuncAttributeMaxDynamicSharedMemorySize, GEMM_SMEM);
    cudaFuncSetAttribute(gemm_tc<M_FC1,256>,  cudaFuncAttributeMaxDynamicSharedMemorySize, GEMM_SMEM);
    cudaFuncSetAttribute(gemm_tc<M_FC2,256>,  cudaFuncAttributeMaxDynamicSharedMemorySize, GEMM_SMEM);
    cudaFuncSetAttribute(attn_tc,             cudaFuncAttributeMaxDynamicSharedMemorySize, ATTN_SMEM);

    ln_kernel<0><<<LTOT, 256>>>(x, n1g, n1b);
    gemm_tc<M_QKV, 128><<<dim3(QKV_ROWS/128, 3), 256, GEMM_SMEM>>>(qkvw, qkvb, (const float*)0, (float*)0);
    gradv_kernel<<<2*BATCH*NWIN, 256>>>();
    attn_tc<<<2*BATCH*128*2, 256, ATTN_SMEM>>>();
    gemm_tc<M_PROJ, 128><<<dim3(QKV_ROWS/128, 1), 256, GEMM_SMEM>>>(projw, projb, x, (float*)0);
    ln_kernel<1><<<LTOT, 256>>>((const float*)0, n2g, n2b);
    gemm_tc<M_FC1, 256><<<dim3(LTOT/128, 4), 256, GEMM_SMEM>>>(fc1w, fc1b, (const float*)0, (float*)0);
    gate_kernel<<<BATCH*HWD, 256>>>(dww, dwb);
    gemm_tc<M_FC2, 256><<<dim3(LTOT/128, 2), 256, GEMM_SMEM>>>(fc2w, fc2b, (const float*)0, out);
}

// round 8
// speedup vs baseline: 2.7454x; 1.1719x over previous
#include <cuda_runtime.h>
#include <cuda_bf16.h>
#include <math.h>
#include <stdint.h>

// ---------------------------------------------------------------------------
// Problem constants
// ---------------------------------------------------------------------------
namespace {
constexpr int BATCH = 8;
constexpr int HWD   = 128;
constexpr int DIM   = 256;
constexpr int NWIN  = 256;
constexpr int NTOK  = 64;
constexpr int LTOT  = BATCH * HWD * HWD;            // 131072
constexpr int QKV_ROWS = 2 * BATCH * NWIN * NTOK;   // 262144
constexpr int HID   = 512;
// bf16 smem: A/B tiles 128 rows x 20 words (32 bf16 + pad), double buffered
constexpr int GEMM_SMEM = 2 * 2 * 128 * 20 * 4;     // 40960 B
// attn: 400 words hdr + Ws 2x128x20 + Vst 2x64x20
constexpr int ATTN_SMEM = (400 + 2*2560 + 2*1280) * 4; // 32320 B
}
#define QSCALE  0.17677669529663687f   /* 32^-0.5 */
#define LOG2E   1.4426950408889634f

// ---------------------------------------------------------------------------
// Scratch (device globals)
// ---------------------------------------------------------------------------
__device__ float g_xn [(size_t)LTOT * DIM];
__device__ float g_qk [(size_t)QKV_ROWS * 256];      // Q,K only (V -> g_vt)
__device__ float g_qg [(size_t)2*8*128*256];
__device__ float g_kg [(size_t)2*8*128*256];
__device__ float g_vt [(size_t)2*8*128*256*64];      // (p,b,c,win,tok)
__device__ float g_ao [(size_t)QKV_ROWS * 128];
__device__ float g_y  [(size_t)LTOT * DIM];
__device__ float g_z  [(size_t)LTOT * DIM];
__device__ float g_t  [(size_t)LTOT * HID];
__device__ float g_g  [(size_t)LTOT * DIM];

// ---------------------------------------------------------------------------
// Window row -> spatial index (roll handled; self-inverse map)
// ---------------------------------------------------------------------------
__device__ __forceinline__ size_t spatial_idx(int r) {
    int p   = r >> 17;
    int rem = r & 131071;
    int b   = rem >> 14;
    int win = (rem >> 6) & 255;
    int t   = rem & 63;
    int hh  = ((win >> 4) << 3) + (t >> 3);
    int ww  = ((win & 15) << 3) + (t & 7);
    if (p) { hh = (hh + 4) & 127; ww = (ww + 4) & 127; }
    return ((size_t)(b * 16384 + hh * 128 + ww)) * 256 + p * 128;
}

// ---------------------------------------------------------------------------
// bf16 helpers
// ---------------------------------------------------------------------------
__device__ __forceinline__ uint32_t pack_bf16(float lo, float hi) {
    __nv_bfloat162 p = __floats2bfloat162_rn(lo, hi);   // .x=lo (low half)
    return *reinterpret_cast<uint32_t*>(&p);
}
__device__ __forceinline__ void mma16(float* c, const uint32_t* a,
                                      uint32_t b0, uint32_t b1) {
    asm volatile(
        "mma.sync.aligned.m16n8k16.row.col.f32.bf16.bf16.f32 "
        "{%0,%1,%2,%3},{%4,%5,%6,%7},{%8,%9},{%0,%1,%2,%3};"
        : "+f"(c[0]), "+f"(c[1]), "+f"(c[2]), "+f"(c[3])
        : "r"(a[0]), "r"(a[1]), "r"(a[2]), "r"(a[3]), "r"(b0), "r"(b1));
}

// ---------------------------------------------------------------------------
// LayerNorm
// ---------------------------------------------------------------------------
template <int MODE>
__global__ __launch_bounds__(256) void ln_kernel(
    const float* __restrict__ in_ext,
    const float* __restrict__ gamma, const float* __restrict__ beta)
{
    __shared__ float s1[8], s2[8];
    const float* in = (MODE == 0) ? in_ext : g_y;
    float* out      = (MODE == 0) ? g_xn  : g_z;
    size_t base = (size_t)blockIdx.x * 256;
    int tid = threadIdx.x;
    float v = in[base + tid];
    float a = v, q = v * v;
    #pragma unroll
    for (int o = 16; o > 0; o >>= 1) {
        a += __shfl_xor_sync(0xffffffffu, a, o);
        q += __shfl_xor_sync(0xffffffffu, q, o);
    }
    if ((tid & 31) == 0) { s1[tid >> 5] = a; s2[tid >> 5] = q; }
    __syncthreads();
    float suma = 0.f, sumq = 0.f;
    #pragma unroll
    for (int w = 0; w < 8; w++) { suma += s1[w]; sumq += s2[w]; }
    float mean = suma * (1.f / 256.f);
    float var  = sumq * (1.f / 256.f) - mean * mean;
    float inv  = rsqrtf(var + 1e-5f);
    out[base + tid] = (v - mean) * inv * gamma[tid] + beta[tid];
}

// ---------------------------------------------------------------------------
// bf16 GEMM, double-buffered (1 bar/chunk). C = A @ W^T (+bias, +epilogue)
// 128x128 tile, BK=32, 256 threads. Smem rows: 20 words (32 bf16 + 4 pad)
// -> fragment loads are verified conflict-free (g*20+tg covers all banks).
// ---------------------------------------------------------------------------
enum { M_QKV = 0, M_PROJ = 1, M_FC2 = 2, M_FC1 = 3 };

#define ATS(b,m,k) dsm[(b)*2560 + (m)*20 + (k)]
#define BTS(b,m,k) dsm[5120 + (b)*2560 + (m)*20 + (k)]

template <int MODE, int K>
__global__ __launch_bounds__(256, 2) void gemm_tc(
    const float* __restrict__ Wt,
    const float* __restrict__ bias,
    const float* __restrict__ ext_in,
    float* __restrict__ ext_out)
{
    extern __shared__ uint32_t dsm[];
    const int tid = threadIdx.x, lane = tid & 31, warp = tid >> 5;
    const int wm = warp >> 1, wn = warp & 1;
    const int g = lane >> 2, tg = lane & 3;
    const int m0 = blockIdx.x * 128, n0 = blockIdx.y * 128;
    constexpr int NC = K / 32;

    const float* Abase =
        (MODE == M_PROJ) ? g_ao :
        (MODE == M_FC1)  ? g_z  :
        (MODE == M_FC2)  ? g_g  : (const float*)0;

    float c[2][8][4];
    #pragma unroll
    for (int mi = 0; mi < 2; mi++)
        #pragma unroll
        for (int ni = 0; ni < 8; ni++)
            #pragma unroll
            for (int k = 0; k < 4; k++) c[mi][ni][k] = 0.f;

    const int lm = tid >> 3, lq = tid & 7;
    const float* arow[4];
    const float* brow[4];
    #pragma unroll
    for (int i = 0; i < 4; i++) {
        int m = lm + 32 * i;
        arow[i] = (MODE == M_QKV) ? (g_xn + spatial_idx(m0 + m))
                                  : (Abase + (size_t)(m0 + m) * K);
        brow[i] = Wt + (size_t)(n0 + m) * K;
    }

    float4 pa[4], pbf[4];
    #pragma unroll
    for (int i = 0; i < 4; i++) {
        pa[i]  = *(const float4*)(arow[i] + lq * 4);
        pbf[i] = *(const float4*)(brow[i] + lq * 4);
    }
    #pragma unroll
    for (int i = 0; i < 4; i++) {
        int m = lm + 32 * i;
        *(uint2*)&ATS(0, m, lq * 2) =
            make_uint2(pack_bf16(pa[i].x, pa[i].y),  pack_bf16(pa[i].z, pa[i].w));
        *(uint2*)&BTS(0, m, lq * 2) =
            make_uint2(pack_bf16(pbf[i].x, pbf[i].y), pack_bf16(pbf[i].z, pbf[i].w));
    }
    __syncthreads();
    if (NC > 1) {
        #pragma unroll
        for (int i = 0; i < 4; i++) {
            pa[i]  = *(const float4*)(arow[i] + 32 + lq * 4);
            pbf[i] = *(const float4*)(brow[i] + 32 + lq * 4);
        }
    }

    for (int ic = 0; ic < NC; ic++) {
        int cur = ic & 1, nxt = cur ^ 1;
        if (ic < NC - 1) {
            #pragma unroll
            for (int i = 0; i < 4; i++) {
                int m = lm + 32 * i;
                *(uint2*)&ATS(nxt, m, lq * 2) =
                    make_uint2(pack_bf16(pa[i].x, pa[i].y),  pack_bf16(pa[i].z, pa[i].w));
                *(uint2*)&BTS(nxt, m, lq * 2) =
                    make_uint2(pack_bf16(pbf[i].x, pbf[i].y), pack_bf16(pbf[i].z, pbf[i].w));
            }
            if (ic < NC - 2) {
                int koff = (ic + 2) * 32 + lq * 4;
                #pragma unroll
                for (int i = 0; i < 4; i++) {
                    pa[i]  = *(const float4*)(arow[i] + koff);
                    pbf[i] = *(const float4*)(brow[i] + koff);
                }
            }
        }
        // 2 k-steps of 16: wbase in {0, 8} words
        #pragma unroll
        for (int ks = 0; ks < 2; ks++) {
            int wbase = ks * 8;
            uint32_t a[2][4];
            #pragma unroll
            for (int mi = 0; mi < 2; mi++) {
                int r = wm * 32 + mi * 16;
                a[mi][0] = ATS(cur, r + g,     wbase + tg);
                a[mi][1] = ATS(cur, r + 8 + g, wbase + tg);
                a[mi][2] = ATS(cur, r + g,     wbase + 4 + tg);
                a[mi][3] = ATS(cur, r + 8 + g, wbase + 4 + tg);
            }
            #pragma unroll
            for (int ni = 0; ni < 8; ni++) {
                int cb = wn * 64 + ni * 8;
                uint32_t b0 = BTS(cur, cb + g, wbase + tg);
                uint32_t b1 = BTS(cur, cb + g, wbase + 4 + tg);
                mma16(c[0][ni], a[0], b0, b1);
                mma16(c[1][ni], a[1], b0, b1);
            }
        }
        __syncthreads();
    }

    #pragma unroll
    for (int mi = 0; mi < 2; mi++) {
        int rr0 = m0 + wm * 32 + mi * 16 + g;
        int rr1 = rr0 + 8;
        size_t sp0 = 0, sp1 = 0;
        if (MODE == M_PROJ) { sp0 = spatial_idx(rr0); sp1 = spatial_idx(rr1); }
        size_t vb0 = 0, vb1 = 0;
        if (MODE == M_QKV && n0 == 256) {
            int pb0 = rr0 >> 14, w0 = (rr0 >> 6) & 255, t0 = rr0 & 63;
            int pb1 = rr1 >> 14, w1 = (rr1 >> 6) & 255, t1 = rr1 & 63;
            vb0 = (((size_t)pb0 * 128) * 256 + w0) * 64 + t0;
            vb1 = (((size_t)pb1 * 128) * 256 + w1) * 64 + t1;
        }
        #pragma unroll
        for (int ni = 0; ni < 8; ni++) {
            int col = n0 + wn * 64 + ni * 8 + 2 * tg;
            float2 bb = *(const float2*)(bias + col);
            float v00 = c[mi][ni][0] + bb.x, v01 = c[mi][ni][1] + bb.y;
            float v10 = c[mi][ni][2] + bb.x, v11 = c[mi][ni][3] + bb.y;
            if (MODE == M_QKV) {
                if (n0 < 256) {
                    *(float2*)&g_qk[(size_t)rr0 * 256 + col] = make_float2(v00, v01);
                    *(float2*)&g_qk[(size_t)rr1 * 256 + col] = make_float2(v10, v11);
                } else {
                    size_t cv = (size_t)(col - 256) * 16384;
                    g_vt[vb0 + cv]         = v00;
                    g_vt[vb0 + cv + 16384] = v01;
                    g_vt[vb1 + cv]         = v10;
                    g_vt[vb1 + cv + 16384] = v11;
                }
            } else if (MODE == M_PROJ) {
                size_t i0 = sp0 + col, i1 = sp1 + col;
                float2 s0 = *(const float2*)(ext_in + i0);
                float2 s1 = *(const float2*)(ext_in + i1);
                *(float2*)&g_y[i0] = make_float2(s0.x + v00, s0.y + v01);
                *(float2*)&g_y[i1] = make_float2(s1.x + v10, s1.y + v11);
            } else if (MODE == M_FC1) {
                *(float2*)&g_t[(size_t)rr0 * 512 + col] = make_float2(v00, v01);
                *(float2*)&g_t[(size_t)rr1 * 512 + col] = make_float2(v10, v11);
            } else { // M_FC2
                size_t i0 = (size_t)rr0 * 256 + col, i1 = (size_t)rr1 * 256 + col;
                float2 y0 = *(const float2*)&g_y[i0];
                float2 y1 = *(const float2*)&g_y[i1];
                *(float2*)&ext_out[i0] = make_float2(y0.x + v00, y0.y + v01);
                *(float2*)&ext_out[i1] = make_float2(y1.x + v10, y1.y + v11);
            }
        }
    }
}

// ---------------------------------------------------------------------------
// Grad scores (Q,K). One block per (p,b,win) = 4096 blocks.
// ---------------------------------------------------------------------------
__global__ __launch_bounds__(256) void gradv_kernel() {
    __shared__ float buf[64][130];
    int blk = blockIdx.x;
    int pb  = blk >> 8;
    int win = blk & 255;
    const float* qk = g_qk + (size_t)blk * 64 * 256;
    int tid = threadIdx.x;

    #pragma unroll
    for (int phase = 0; phase < 2; phase++) {
        for (int idx = tid; idx < 64*128; idx += 256)
            buf[idx >> 7][idx & 127] = qk[(size_t)(idx >> 7) * 256 + phase*128 + (idx & 127)];
        __syncthreads();
        if (tid < 128) {
            float s = 0.f;
            #pragma unroll
            for (int tr = 0; tr < 8; tr++)
                #pragma unroll
                for (int tc = 0; tc < 8; tc++) {
                    float v = buf[tr*8+tc][tid];
                    float l = tc ? buf[tr*8+tc-1][tid] : 0.f;
                    float u = tr ? buf[(tr-1)*8+tc][tid] : 0.f;
                    s += fabsf(v - l) + fabsf(v - u);
                }
            size_t o = ((size_t)pb * 128 + tid) * 256 + win;
            if (phase == 0) g_qg[o] = s * QSCALE;
            else            g_kg[o] = s;
        }
        __syncthreads();
    }
}

// ---------------------------------------------------------------------------
// bf16 tensor-core attention, double-buffered + V register prefetch.
// Grid = 4096: block = (pb,c) x m-half.  O = softmax(qg kg^T) V per channel.
// Words: kg_s[256] | zrow[128] | red[16] | Ws 2x128x20 | Vst 2x64x20
// ---------------------------------------------------------------------------
#define WSM(b,r,j) dsm[400 + (b)*2560 + (r)*20 + (j)]
#define VSM(b,t,j) dsm[5520 + (b)*1280 + (t)*20 + (j)]

__global__ __launch_bounds__(256, 3) void attn_tc() {
    extern __shared__ uint32_t dsm[];
    float* kg_s = (float*)dsm;
    float* zrow = (float*)(dsm + 256);
    float* red  = (float*)(dsm + 384);
    int bx = blockIdx.x;
    int mhalf = bx & 1;
    int blk = bx >> 1;
    int c  = blk & 127;
    int pb = blk >> 7;
    int tid = threadIdx.x, lane = tid & 31, warp = tid >> 5;
    int g = lane >> 2, tg = lane & 3;
    const float* kg = g_kg + (size_t)blk * 256;
    const float* qg = g_qg + (size_t)blk * 256;
    const float* v  = g_vt + (size_t)blk * (256 * 64);

    // kg + block max
    float kv = kg[tid];
    kg_s[tid] = kv;
    float km = kv;
    #pragma unroll
    for (int o = 16; o > 0; o >>= 1)
        km = fmaxf(km, __shfl_xor_sync(0xffffffffu, km, o));
    if (lane == 0) red[warp] = km;
    __syncthreads();
    km = red[0];
    #pragma unroll
    for (int w = 1; w < 8; w++) km = fmaxf(km, red[w]);

    int erow  = tid >> 1;            // row within m-half
    int ehalf = tid & 1;             // j half (16 each)
    const int jp = tid >> 6;         // 0..3: j pair group for V loads
    const int vt = tid & 63;         // token for V loads
    float qg2 = qg[mhalf * 128 + erow] * LOG2E;
    float m2  = qg2 * km;
    float zacc = 0.f;

    float acc[8][4];
    #pragma unroll
    for (int ni = 0; ni < 8; ni++)
        #pragma unroll
        for (int k = 0; k < 4; k++) acc[ni][k] = 0.f;

    // ---- prologue: chunk 0 into buffer 0
    #pragma unroll
    for (int q8 = 0; q8 < 8; q8++) {
        int j0 = ehalf * 16 + q8 * 2;
        float w0 = exp2f(fmaf(qg2, kg_s[j0],     -m2));
        float w1 = exp2f(fmaf(qg2, kg_s[j0 + 1], -m2));
        zacc += w0 + w1;
        WSM(0, erow, ehalf * 8 + q8) = pack_bf16(w0, w1);
    }
    #pragma unroll
    for (int e = 0; e < 4; e++) {
        int j0 = e * 8 + jp * 2;
        float f0 = v[(size_t)j0 * 64 + vt];
        float f1 = v[(size_t)(j0 + 1) * 64 + vt];
        VSM(0, vt, e * 4 + jp) = pack_bf16(f0, f1);
    }
    __syncthreads();

    float vreg[8];
    #pragma unroll
    for (int e = 0; e < 4; e++) {
        int j0 = 32 + e * 8 + jp * 2;
        vreg[e*2]   = v[(size_t)j0 * 64 + vt];
        vreg[e*2+1] = v[(size_t)(j0 + 1) * 64 + vt];
    }

    for (int ic = 0; ic < 8; ic++) {
        int cur = ic & 1, nxt = cur ^ 1;
        if (ic < 7) {
            #pragma unroll
            for (int e = 0; e < 4; e++)
                VSM(nxt, vt, e * 4 + jp) = pack_bf16(vreg[e*2], vreg[e*2+1]);
            if (ic < 6) {
                int kcv = (ic + 2) * 32;
                #pragma unroll
                for (int e = 0; e < 4; e++) {
                    int j0 = kcv + e * 8 + jp * 2;
                    vreg[e*2]   = v[(size_t)j0 * 64 + vt];
                    vreg[e*2+1] = v[(size_t)(j0 + 1) * 64 + vt];
                }
            }
            int kcn = (ic + 1) * 32;
            #pragma unroll
            for (int q8 = 0; q8 < 8; q8++) {
                int j0 = kcn + ehalf * 16 + q8 * 2;
                float w0 = exp2f(fmaf(qg2, kg_s[j0],     -m2));
                float w1 = exp2f(fmaf(qg2, kg_s[j0 + 1], -m2));
                zacc += w0 + w1;
                WSM(nxt, erow, ehalf * 8 + q8) = pack_bf16(w0, w1);
            }
        }
        // 2 k-steps of 16 over the 32-j chunk
        #pragma unroll
        for (int ks = 0; ks < 2; ks++) {
            int wbase = ks * 8;
            uint32_t a[4];
            int r = warp * 16;
            a[0] = WSM(cur, r + g,     wbase + tg);
            a[1] = WSM(cur, r + 8 + g, wbase + tg);
            a[2] = WSM(cur, r + g,     wbase + 4 + tg);
            a[3] = WSM(cur, r + 8 + g, wbase + 4 + tg);
            #pragma unroll
            for (int ni = 0; ni < 8; ni++) {
                uint32_t b0 = VSM(cur, ni * 8 + g, wbase + tg);
                uint32_t b1 = VSM(cur, ni * 8 + g, wbase + 4 + tg);
                mma16(acc[ni], a, b0, b1);
            }
        }
        __syncthreads();
    }

    // Z per row (pair-sum), normalize, store
    zacc += __shfl_xor_sync(0xffffffffu, zacc, 1);
    if (ehalf == 0) zrow[erow] = zacc;
    __syncthreads();

    int r0l = warp * 16 + g, r1l = r0l + 8;
    float iz0 = 1.f / zrow[r0l];
    float iz1 = 1.f / zrow[r1l];
    int i0 = mhalf * 128 + r0l, i1 = mhalf * 128 + r1l;
    size_t ob0 = (((size_t)pb * 256 + i0) * 64) * 128 + c;
    size_t ob1 = (((size_t)pb * 256 + i1) * 64) * 128 + c;
    #pragma unroll
    for (int ni = 0; ni < 8; ni++) {
        int t = ni * 8 + 2 * tg;
        g_ao[ob0 + (size_t)t * 128]       = acc[ni][0] * iz0;
        g_ao[ob0 + (size_t)(t + 1) * 128] = acc[ni][1] * iz0;
        g_ao[ob1 + (size_t)t * 128]       = acc[ni][2] * iz1;
        g_ao[ob1 + (size_t)(t + 1) * 128] = acc[ni][3] * iz1;
    }
}

// ---------------------------------------------------------------------------
// Depthwise 3x3 + gate, sliding-column register window (6 LDG/output)
// ---------------------------------------------------------------------------
__global__ __launch_bounds__(256) void gate_kernel(
    const float* __restrict__ dww, const float* __restrict__ dwb)
{
    int bh = blockIdx.x;
    int b  = bh >> 7;
    int hh = bh & 127;
    int c  = threadIdx.x;
    float w1[9], w2[9];
    #pragma unroll
    for (int k = 0; k < 9; k++) {
        w1[k] = dww[c*9 + k];
        w2[k] = dww[(c+256)*9 + k];
    }
    float b1 = dwb[c], b2 = dwb[c+256];
    const float* tb = g_t + (size_t)b * 16384 * 512;
    float* gout = g_g + ((size_t)b * 16384 + hh * 128) * 256 + c;

    float cA[3][3], cB[3][3];   // [colpos m/0/p][row]
    #pragma unroll
    for (int r = 0; r < 3; r++) { cA[0][r] = 0.f; cB[0][r] = 0.f; }
    #pragma unroll
    for (int r = 0; r < 3; r++) {
        int hy = hh - 1 + r;
        bool ok = (unsigned)hy < 128u;
        size_t off = ((size_t)hy * 128 + 0) * 512;
        cA[1][r] = ok ? tb[off + c]       : 0.f;
        cB[1][r] = ok ? tb[off + 256 + c] : 0.f;
        cA[2][r] = ok ? tb[off + 512 + c]       : 0.f;
        cB[2][r] = ok ? tb[off + 512 + 256 + c] : 0.f;
    }

    for (int ww = 0; ww < 128; ww++) {
        float s1 = b1, s2 = b2;
        #pragma unroll
        for (int r = 0; r < 3; r++) {
            s1 = fmaf(cA[0][r], w1[r*3+0], s1);
            s1 = fmaf(cA[1][r], w1[r*3+1], s1);
            s1 = fmaf(cA[2][r], w1[r*3+2], s1);
            s2 = fmaf(cB[0][r], w2[r*3+0], s2);
            s2 = fmaf(cB[1][r], w2[r*3+1], s2);
            s2 = fmaf(cB[2][r], w2[r*3+2], s2);
        }
        gout[(size_t)ww * 256] = s1 * s2;
        int wx = ww + 2;
        bool okx = wx < 128;
        #pragma unroll
        for (int r = 0; r < 3; r++) {
            cA[0][r] = cA[1][r]; cA[1][r] = cA[2][r];
            cB[0][r] = cB[1][r]; cB[1][r] = cB[2][r];
            int hy = hh - 1 + r;
            bool ok = okx && (unsigned)hy < 128u;
            size_t off = ((size_t)hy * 128 + wx) * 512;
            cA[2][r] = ok ? tb[off + c]       : 0.f;
            cB[2][r] = ok ? tb[off + 256 + c] : 0.f;
        }
    }
}

// ---------------------------------------------------------------------------
// Launch (attribute calls unconditional — no static guards)
// ---------------------------------------------------------------------------
extern "C" void kernel_launch(void* const* d_in, const int* in_sizes, int n_in,
                              void* d_out, int out_size) {
    (void)in_sizes; (void)n_in; (void)out_size;
    const float* x     = (const float*)d_in[0];
    const float* n1g   = (const float*)d_in[1];
    const float* n1b   = (const float*)d_in[2];
    const float* qkvw  = (const float*)d_in[3];
    const float* qkvb  = (const float*)d_in[4];
    const float* projw = (const float*)d_in[5];
    const float* projb = (const float*)d_in[6];
    const float* n2g   = (const float*)d_in[7];
    const float* n2b   = (const float*)d_in[8];
    const float* fc1w  = (const float*)d_in[9];
    const float* fc1b  = (const float*)d_in[10];
    const float* dww   = (const float*)d_in[11];
    const float* dwb   = (const float*)d_in[12];
    const float* fc2w  = (const float*)d_in[13];
    const float* fc2b  = (const float*)d_in[14];
    float* out = (float*)d_out;

    cudaFuncSetAttribute(gemm_tc<M_QKV,128>,  cudaFuncAttributeMaxDynamicSharedMemorySize, GEMM_SMEM);
    cudaFuncSetAttribute(gemm_tc<M_PROJ,128>, cudaFuncAttributeMaxDynamicSharedMemorySize, GEMM_SMEM);
    cudaFuncSetAttribute(gemm_tc<M_FC1,256>,  cudaFuncAttributeMaxDynamicSharedMemorySize, GEMM_SMEM);
    cudaFuncSetAttribute(gemm_tc<M_FC2,256>,  cudaFuncAttributeMaxDynamicSharedMemorySize, GEMM_SMEM);
    cudaFuncSetAttribute(attn_tc,             cudaFuncAttributeMaxDynamicSharedMemorySize, ATTN_SMEM);

    ln_kernel<0><<<LTOT, 256>>>(x, n1g, n1b);
    gemm_tc<M_QKV, 128><<<dim3(QKV_ROWS/128, 3), 256, GEMM_SMEM>>>(qkvw, qkvb, (const float*)0, (float*)0);
    gradv_kernel<<<2*BATCH*NWIN, 256>>>();
    attn_tc<<<2*BATCH*128*2, 256, ATTN_SMEM>>>();
    gemm_tc<M_PROJ, 128><<<dim3(QKV_ROWS/128, 1), 256, GEMM_SMEM>>>(projw, projb, x, (float*)0);
    ln_kernel<1><<<LTOT, 256>>>((const float*)0, n2g, n2b);
    gemm_tc<M_FC1, 256><<<dim3(LTOT/128, 4), 256, GEMM_SMEM>>>(fc1w, fc1b, (const float*)0, (float*)0);
    gate_kernel<<<BATCH*HWD, 256>>>(dww, dwb);
    gemm_tc<M_FC2, 256><<<dim3(LTOT/128, 2), 256, GEMM_SMEM>>>(fc2w, fc2b, (const float*)0, out);
}